// round 5
// baseline (speedup 1.0000x reference)
#include <cuda_runtime.h>
#include <cstdint>

// ---------------- problem constants ----------------
#define T_TOK 8192          // B*S
#define H_DIM 1024
#define E_NUM 8
#define I_DIM 4096
#define NT 512              // threads per GEMM CTA

// tcgen05 only legal in the sm_103a arch-accelerated pass
#if !defined(__CUDA_ARCH__) || defined(__CUDA_ARCH_FEAT_SM103_ALL)
#define HAS_TC 1
#else
#define HAS_TC 0
#endif

// ---------------- device scratch (static, allocation-free) ----------------
__device__ int   g_count[E_NUM];
__device__ int   g_tok[E_NUM * T_TOK];
__device__ float g_wt [E_NUM * T_TOK];
__device__ float g_h  [268435456];                       // [E*T, I]  1.07GB
__device__ float g_xa [(size_t)E_NUM * T_TOK * H_DIM];   // gathered+rounded x
__device__ float g_w1t[(size_t)E_NUM * I_DIM * H_DIM];   // [E][I][H] rounded
__device__ float g_w3t[(size_t)E_NUM * I_DIM * H_DIM];
__device__ float g_w2t[(size_t)E_NUM * H_DIM * I_DIM];   // [E][H][I] rounded

// ---------------- common helpers ----------------
__device__ __forceinline__ float to_tf32(float f) {
    uint32_t u;
    asm("cvt.rna.tf32.f32 %0, %1;" : "=r"(u) : "f"(f));
    return __uint_as_float(u);
}
#define SW128(x) ((x) ^ (((x) >> 3) & 0x70))

#if HAS_TC
__device__ __forceinline__ uint32_t smem_u32(const void* p) {
    uint32_t a;
    asm("{ .reg .u64 t; cvta.to.shared.u64 t, %1; cvt.u32.u64 %0, t; }"
        : "=r"(a) : "l"(p));
    return a;
}
__device__ __forceinline__ uint32_t elect1() {
    uint32_t p;
    asm volatile("{ .reg .pred p; elect.sync _|p, 0xFFFFFFFF; selp.b32 %0,1,0,p; }" : "=r"(p));
    return p;
}
__device__ __forceinline__ uint32_t ctarank() {
    uint32_t r;
    asm("mov.u32 %0, %%cluster_ctarank;" : "=r"(r));
    return r;
}
__device__ __forceinline__ void cpa16(uint32_t dst, const float* src) {
    asm volatile("cp.async.cg.shared.global [%0], [%1], 16;" :: "r"(dst), "l"(src));
}
#define CP_COMMIT() asm volatile("cp.async.commit_group;" ::: "memory")
#define CP_WAIT3()  asm volatile("cp.async.wait_group 3;" ::: "memory")
#define CP_WAIT2()  asm volatile("cp.async.wait_group 2;" ::: "memory")
#define CP_WAIT1()  asm volatile("cp.async.wait_group 1;" ::: "memory")
#define CP_WAIT0()  asm volatile("cp.async.wait_group 0;" ::: "memory")

// SW128 K-major smem descriptor (Blackwell): layout=2, version=1, SBO=64, LBO=1
static constexpr uint64_t DESC_BASE =
    (2ull << 61) | (1ull << 46) | (64ull << 32) | (1ull << 16);
__device__ __forceinline__ uint64_t mkdesc(uint32_t smem_addr) {
    return DESC_BASE | ((uint64_t)(smem_addr >> 4) & 0x3FFF);
}
// cg2 idesc: D=F32(1<<4), A=TF32(2<<7), B=TF32(2<<10), N=256 (32<<17), M=256 (16<<24)
static constexpr uint32_t IDESC2 =
    (1u << 4) | (2u << 7) | (2u << 10) | (32u << 17) | (16u << 24);

__device__ __forceinline__ void mma2_tf32(uint32_t d, uint64_t a, uint64_t b,
                                          uint32_t en) {
    asm volatile(
        "{\n\t"
        ".reg .pred p;\n\t"
        "setp.ne.u32 p, %4, 0;\n\t"
        "tcgen05.mma.cta_group::2.kind::tf32 [%0], %1, %2, %3, "
        "{%5,%5,%5,%5,%5,%5,%5,%5}, p;\n\t"
        "}"
        :: "r"(d), "l"(a), "l"(b), "r"(IDESC2), "r"(en), "r"(0u)
        : "memory");
}

#define TCGEN05_ALLOC_CG2(a, n) \
    asm volatile("tcgen05.alloc.cta_group::2.sync.aligned.shared::cta.b32 [%0], %1;" \
        :: "r"((uint32_t)(a)), "r"((uint32_t)(n)) : "memory")
#define TCGEN05_RELINQ_CG2() \
    asm volatile("tcgen05.relinquish_alloc_permit.cta_group::2.sync.aligned;")
#define TCGEN05_DEALLOC_CG2(t, n) \
    asm volatile("tcgen05.dealloc.cta_group::2.sync.aligned.b32 %0, %1;" \
        :: "r"(t), "r"((uint32_t)(n)))
#define TCGEN05_COMMIT_MCAST2(mbar) \
    asm volatile("tcgen05.commit.cta_group::2.mbarrier::arrive::one.shared::cluster.multicast::cluster.b64 [%0], %1;" \
        :: "r"((uint32_t)(mbar)), "h"((uint16_t)0x3) : "memory")
#define TCGEN05_FENCE_AFTER() \
    asm volatile("tcgen05.fence::after_thread_sync;" ::: "memory")
#define TCGEN05_WAIT_LD() \
    asm volatile("tcgen05.wait::ld.sync.aligned;" ::: "memory")
#define FENCE_ASYNC_ALL() \
    asm volatile("fence.proxy.async;" ::: "memory")

#define MBARRIER_INIT(a, c) \
    asm volatile("mbarrier.init.shared.b64 [%0], %1;" \
        :: "r"((uint32_t)(a)), "r"((uint32_t)(c)) : "memory")
#define MBARRIER_INVAL(a) \
    asm volatile("mbarrier.inval.shared.b64 [%0];" \
        :: "r"((uint32_t)(a)) : "memory")
// arrive on rank0's barrier at same smem offset (works from either rank)
#define ARRIVE_RANK0(addr) \
    asm volatile( \
        "{\n\t.reg .b32 r;\n\t" \
        "mapa.shared::cluster.u32 r, %0, 0;\n\t" \
        "mbarrier.arrive.shared::cluster.b64 _, [r];\n\t}" \
        :: "r"((uint32_t)(addr)) : "memory")
#define CLUSTER_SYNC() do { \
    asm volatile("barrier.cluster.arrive.aligned;" ::: "memory"); \
    asm volatile("barrier.cluster.wait.aligned;" ::: "memory"); \
} while (0)

#define MBARRIER_WAIT_PARITY(mbar_smem_addr, phase_parity) do { \
    uint32_t _mbar = (uint32_t)(mbar_smem_addr); \
    uint32_t _parity = (uint32_t)(phase_parity); \
    uint32_t _done; \
    asm volatile( \
        "{\n\t" \
        ".reg .pred p;\n\t" \
        "mbarrier.try_wait.parity.acquire.cta.shared::cta.b64 p, [%1], %2;\n\t" \
        "selp.b32 %0, 1, 0, p;\n\t" \
        "}" \
        : "=r"(_done) : "r"(_mbar), "r"(_parity) : "memory"); \
    if (!_done) { \
        asm volatile( \
            "{\n\t" \
            ".reg .pred P1;\n\t" \
            "WAIT_LOOP_%=:\n\t" \
            "mbarrier.try_wait.parity.acquire.cta.shared::cta.b64 P1, [%0], %1, 0x989680;\n\t" \
            "@P1 bra.uni WAIT_DONE_%=;\n\t" \
            "bra.uni WAIT_LOOP_%=;\n\t" \
            "WAIT_DONE_%=:\n\t" \
            "}" \
            :: "r"(_mbar), "r"(_parity) : "memory"); \
    } \
} while (0)

#define TCGEN05_LD_32X32B_X32(r, tmem_addr) \
    asm volatile( \
        "tcgen05.ld.sync.aligned.32x32b.x32.b32 " \
        "{%0, %1, %2, %3, %4, %5, %6, %7, " \
        " %8, %9, %10, %11, %12, %13, %14, %15, " \
        " %16, %17, %18, %19, %20, %21, %22, %23, " \
        " %24, %25, %26, %27, %28, %29, %30, %31}, [%32];" \
        : "=r"((r)[0]),  "=r"((r)[1]),  "=r"((r)[2]),  "=r"((r)[3]), \
          "=r"((r)[4]),  "=r"((r)[5]),  "=r"((r)[6]),  "=r"((r)[7]), \
          "=r"((r)[8]),  "=r"((r)[9]),  "=r"((r)[10]), "=r"((r)[11]), \
          "=r"((r)[12]), "=r"((r)[13]), "=r"((r)[14]), "=r"((r)[15]), \
          "=r"((r)[16]), "=r"((r)[17]), "=r"((r)[18]), "=r"((r)[19]), \
          "=r"((r)[20]), "=r"((r)[21]), "=r"((r)[22]), "=r"((r)[23]), \
          "=r"((r)[24]), "=r"((r)[25]), "=r"((r)[26]), "=r"((r)[27]), \
          "=r"((r)[28]), "=r"((r)[29]), "=r"((r)[30]), "=r"((r)[31]) \
        : "r"(tmem_addr))
#endif  // HAS_TC

// ---------------- kernel 0: zero out + counters ----------------
__global__ void k_zero(float* __restrict__ out) {
    size_t i = (size_t)blockIdx.x * blockDim.x + threadIdx.x;
    float4* o4 = (float4*)out;
    if (i < (size_t)T_TOK * H_DIM / 4) o4[i] = make_float4(0.f, 0.f, 0.f, 0.f);
    if (blockIdx.x == 0 && threadIdx.x < E_NUM) g_count[threadIdx.x] = 0;
}

// ---------------- kernel 1: gating (softmax top-2, routing lists) ----------------
__global__ void k_gate(const float* __restrict__ x, const float* __restrict__ gw) {
    int t = blockIdx.x;
    const float* xr = x + (size_t)t * H_DIM;
    float acc[E_NUM];
#pragma unroll
    for (int e = 0; e < E_NUM; e++) acc[e] = 0.f;
    for (int h = threadIdx.x; h < H_DIM; h += 256) {
        float xv = xr[h];
        const float* g = gw + h * E_NUM;
#pragma unroll
        for (int e = 0; e < E_NUM; e++) acc[e] += xv * g[e];
    }
#pragma unroll
    for (int e = 0; e < E_NUM; e++)
#pragma unroll
        for (int off = 16; off > 0; off >>= 1)
            acc[e] += __shfl_xor_sync(0xFFFFFFFF, acc[e], off);
    __shared__ float red[8][E_NUM];
    int wid = threadIdx.x >> 5, lid = threadIdx.x & 31;
    if (lid == 0)
#pragma unroll
        for (int e = 0; e < E_NUM; e++) red[wid][e] = acc[e];
    __syncthreads();
    if (threadIdx.x == 0) {
        float l[E_NUM];
#pragma unroll
        for (int e = 0; e < E_NUM; e++) {
            float s = 0.f;
#pragma unroll
            for (int w = 0; w < 8; w++) s += red[w][e];
            l[e] = s;
        }
        int i1 = 0;
#pragma unroll
        for (int e = 1; e < E_NUM; e++) if (l[e] > l[i1]) i1 = e;
        int i2 = (i1 == 0) ? 1 : 0;
#pragma unroll
        for (int e = 0; e < E_NUM; e++) if (e != i1 && l[e] > l[i2]) i2 = e;
        float e2 = expf(l[i2] - l[i1]);
        float wa = 1.f / (1.f + e2);
        float wb = 1.f - wa;
        int p1 = atomicAdd(&g_count[i1], 1);
        g_tok[i1 * T_TOK + p1] = t;  g_wt[i1 * T_TOK + p1] = wa;
        int p2 = atomicAdd(&g_count[i2], 1);
        g_tok[i2 * T_TOK + p2] = t;  g_wt[i2 * T_TOK + p2] = wb;
    }
}

// ---------------- prep: transpose + tf32-round weights ----------------
__global__ void k_tr13(const float* __restrict__ w1, const float* __restrict__ w3) {
    __shared__ float tile[32][33];
    int e = blockIdx.z & 7;
    const float* src = (blockIdx.z < E_NUM ? w1 : w3) + (size_t)e * H_DIM * I_DIM;
    float* dst = (blockIdx.z < E_NUM ? g_w1t : g_w3t) + (size_t)e * I_DIM * H_DIM;
    int i0 = blockIdx.x * 32, h0 = blockIdx.y * 32;
    int tx = threadIdx.x & 31, ty = threadIdx.x >> 5;
#pragma unroll
    for (int r = 0; r < 32; r += 8)
        tile[ty + r][tx] = to_tf32(src[(size_t)(h0 + ty + r) * I_DIM + i0 + tx]);
    __syncthreads();
#pragma unroll
    for (int r = 0; r < 32; r += 8)
        dst[(size_t)(i0 + ty + r) * H_DIM + h0 + tx] = tile[tx][ty + r];
}
__global__ void k_tr2(const float* __restrict__ w2) {
    __shared__ float tile[32][33];
    int e = blockIdx.z;
    const float* src = w2 + (size_t)e * I_DIM * H_DIM;
    float* dst = g_w2t + (size_t)e * H_DIM * I_DIM;
    int h0 = blockIdx.x * 32, i0 = blockIdx.y * 32;
    int tx = threadIdx.x & 31, ty = threadIdx.x >> 5;
#pragma unroll
    for (int r = 0; r < 32; r += 8)
        tile[ty + r][tx] = to_tf32(src[(size_t)(i0 + ty + r) * H_DIM + h0 + tx]);
    __syncthreads();
#pragma unroll
    for (int r = 0; r < 32; r += 8)
        dst[(size_t)(h0 + ty + r) * I_DIM + i0 + tx] = tile[tx][ty + r];
}

// ---------------- pack: gather + round x rows per expert slot ----------------
__global__ void k_pack(const float* __restrict__ x) {
    int e = blockIdx.y;
    int cnt = g_count[e];
    int slot = blockIdx.x * 8 + (threadIdx.x >> 5);
    int c = threadIdx.x & 31;
    if (slot >= cnt) return;
    int tok = g_tok[e * T_TOK + slot];
    const float4* src = (const float4*)(x + (size_t)tok * H_DIM);
    float4* dst = (float4*)(g_xa + ((size_t)e * T_TOK + slot) * H_DIM);
#pragma unroll
    for (int j = 0; j < 8; j++) {
        float4 v = src[c + 32 * j];
        v.x = to_tf32(v.x); v.y = to_tf32(v.y); v.z = to_tf32(v.z); v.w = to_tf32(v.w);
        dst[c + 32 * j] = v;
    }
}

// ---------------- GEMM geometry (cg2 path) ----------------
// Pair tile M=256; K-chunk=32 (4 tf32 K=8 steps); 4-stage cp.async pipeline.
// Stage = 48KB: A(16K, own 128 rows) + B halves (2x16K, N/2 split per CTA).
#define NSTG  4
#define STGB  49152
#define S_BUF 1024
#define SMEM_TOT (S_BUF + NSTG * STGB)   // 197632

// ---------------- grouped GEMM1 (xa@w1t, xa@w3t, SwiGLU -> g_h) --------------
// cluster(2): pair covers 256 slots x 256 I-cols, dual acc d1/d3 (512 TMEM cols)
__global__ void __launch_bounds__(NT, 1) __cluster_dims__(2, 1, 1)
k_gemm1() {
#if HAS_TC
    int e = blockIdx.z, nt = blockIdx.y;
    int mp = blockIdx.x >> 1;
    int cnt = g_count[e];
    if (mp * 256 >= cnt) return;                 // cluster-uniform exit
    uint32_t rank = ctarank();

    extern __shared__ char smem[];
    uint32_t sb = smem_u32(smem);
    int tid = threadIdx.x, wid = tid >> 5, lid = tid & 31;

    if (wid == 0) TCGEN05_ALLOC_CG2(sb, 512);
    if (tid == 0) {
#pragma unroll
        for (int s = 0; s < NSTG; s++) {
            MBARRIER_INIT(sb + 16 + 8 * s, 2);   // ready: 1 arrive per CTA
            MBARRIER_INIT(sb + 48 + 8 * s, 1);   // cmt: commit multicast
        }
    }
    __syncthreads();
    uint32_t tmem;
    asm volatile("ld.shared.b32 %0, [%1];" : "=r"(tmem) : "r"(sb));
    CLUSTER_SYNC();                               // mbars visible cluster-wide

    int n0 = nt * 256;
    const float* Ab  = g_xa  + ((size_t)e * T_TOK + (size_t)mp * 256 + rank * 128) * H_DIM;
    const float* B1b = g_w1t + ((size_t)e * I_DIM + n0 + rank * 128) * H_DIM;
    const float* B3b = g_w3t + ((size_t)e * I_DIM + n0 + rank * 128) * H_DIM;

    auto issue = [&](int st, int kc) {
        uint32_t base = sb + S_BUF + st * STGB;
        int ko = kc * 32;
#pragma unroll
        for (int j = 0; j < 2; j++) {
            int idx = tid + NT * j;
            int r = idx >> 3, c4 = idx & 7;
            cpa16(base + SW128(r * 128 + c4 * 16),         Ab  + (size_t)r * H_DIM + ko + c4 * 4);
            cpa16(base + 16384 + SW128(r * 128 + c4 * 16), B1b + (size_t)r * H_DIM + ko + c4 * 4);
            cpa16(base + 32768 + SW128(r * 128 + c4 * 16), B3b + (size_t)r * H_DIM + ko + c4 * 4);
        }
        CP_COMMIT();
    };

    issue(0, 0); issue(1, 1); issue(2, 2); issue(3, 3);

    const int NK = H_DIM / 32;  // 32
    for (int kc = 0; kc < NK; kc++) {
        int s = kc & 3, p = (kc >> 2) & 1;
        if (kc < NK - 3) CP_WAIT3();
        else if (kc == NK - 3) CP_WAIT2();
        else if (kc == NK - 2) CP_WAIT1();
        else CP_WAIT0();
        __syncthreads();
        if (wid == 0 && elect1()) {
            FENCE_ASYNC_ALL();
            ARRIVE_RANK0(sb + 16 + 8 * s);
            if (rank == 0) {
                MBARRIER_WAIT_PARITY(sb + 16 + 8 * s, p);
                TCGEN05_FENCE_AFTER();
                uint32_t base = sb + S_BUF + s * STGB;
                uint64_t ad  = mkdesc(base);
                uint64_t bd1 = mkdesc(base + 16384);
                uint64_t bd3 = mkdesc(base + 32768);
#pragma unroll
                for (int st4 = 0; st4 < 4; st4++) {
                    uint32_t en = (kc > 0 || st4 > 0) ? 1u : 0u;
                    mma2_tf32(tmem,       ad + st4 * 2, bd1 + st4 * 2, en);
                    mma2_tf32(tmem + 256, ad + st4 * 2, bd3 + st4 * 2, en);
                }
                TCGEN05_COMMIT_MCAST2(sb + 48 + 8 * s);
            }
        }
        if (kc + 4 < NK) {
            MBARRIER_WAIT_PARITY(sb + 48 + 8 * s, p);  // all threads
            issue(s, kc + 4);
        }
    }
#pragma unroll
    for (int s2 = 0; s2 < NSTG; s2++) {
        int kcl = NK - 4 + s2;
        MBARRIER_WAIT_PARITY(sb + 48 + 8 * (kcl & 3), (kcl >> 2) & 1);
    }
    TCGEN05_FENCE_AFTER();

    // epilogue: silu(d1)*d3, tf32-round -> g_h (own 128 lanes)
    int row = (wid & 3) * 32 + lid;
    int slot = mp * 256 + rank * 128 + row;
    bool act = slot < cnt;
    int c0 = (wid >> 2) * 64;
    float* hrow = g_h + ((size_t)e * T_TOK + slot) * I_DIM + n0;
#pragma unroll 1
    for (int cb = 0; cb < 64; cb += 32) {
        uint32_t ra[32], rb[32];
        TCGEN05_LD_32X32B_X32(ra, tmem + c0 + cb);
        TCGEN05_LD_32X32B_X32(rb, tmem + 256 + c0 + cb);
        TCGEN05_WAIT_LD();
        if (act) {
#pragma unroll
            for (int q = 0; q < 32; q += 4) {
                float o[4];
#pragma unroll
                for (int u = 0; u < 4; u++) {
                    float a = __uint_as_float(ra[q + u]);
                    float b = __uint_as_float(rb[q + u]);
                    o[u] = to_tf32((a / (1.0f + expf(-a))) * b);
                }
                *(float4*)(hrow + c0 + cb + q) = make_float4(o[0], o[1], o[2], o[3]);
            }
        }
    }
    __syncthreads();
    if (tid == 0)
#pragma unroll
        for (int s = 0; s < NSTG; s++) {
            MBARRIER_INVAL(sb + 16 + 8 * s);
            MBARRIER_INVAL(sb + 48 + 8 * s);
        }
    __syncthreads();
    CLUSTER_SYNC();
    if (wid == 0) { TCGEN05_RELINQ_CG2(); TCGEN05_DEALLOC_CG2(tmem, 512); }
    CLUSTER_SYNC();
#else
    // ---------- FFMA fallback (per-CTA, cluster attr unused) ----------
    int e = blockIdx.z, nt = blockIdx.y, m = blockIdx.x;
    int cnt = g_count[e];
    if (m * 128 >= cnt) return;
    extern __shared__ char smem[];
    float* As  = (float*)smem;
    float* B1s = As + 2048;
    float* B3s = B1s + 16 * 132;
    int tid = threadIdx.x;
    int tx = tid & 15, ty = tid >> 4;
    int n0 = nt * 256;
    const float* Ab = g_xa + ((size_t)e * T_TOK + (size_t)m * 128) * H_DIM;
    for (int nh = 0; nh < 2; nh++) {
        float a1[4][8], a3[4][8];
#pragma unroll
        for (int i = 0; i < 4; i++)
#pragma unroll
            for (int j = 0; j < 8; j++) { a1[i][j] = 0.f; a3[i][j] = 0.f; }
        for (int kc = 0; kc < H_DIM / 16; kc++) {
            __syncthreads();
#pragma unroll
            for (int L = 0; L < 4; L++) {
                int f = tid + NT * L;
                int row = f >> 4, k = f & 15;
                As[f] = Ab[(size_t)row * H_DIM + kc * 16 + k];
            }
#pragma unroll
            for (int L = 0; L < 4; L++) {
                int f = tid + NT * L;
                int k = f >> 7, c = f & 127;
                B1s[k * 132 + c] = g_w1t[((size_t)e * I_DIM + n0 + nh * 128 + c) * H_DIM + kc * 16 + k];
                B3s[k * 132 + c] = g_w3t[((size_t)e * I_DIM + n0 + nh * 128 + c) * H_DIM + kc * 16 + k];
            }
            __syncthreads();
#pragma unroll
            for (int k = 0; k < 16; k++) {
                float av[4], b1[8], b3[8];
#pragma unroll
                for (int i = 0; i < 4; i++) av[i] = As[(ty * 4 + i) * 16 + k];
#pragma unroll
                for (int j = 0; j < 8; j++) {
                    b1[j] = B1s[k * 132 + tx * 8 + j];
                    b3[j] = B3s[k * 132 + tx * 8 + j];
                }
#pragma unroll
                for (int i = 0; i < 4; i++)
#pragma unroll
                    for (int j = 0; j < 8; j++) {
                        a1[i][j] += av[i] * b1[j];
                        a3[i][j] += av[i] * b3[j];
                    }
            }
        }
#pragma unroll
        for (int i = 0; i < 4; i++) {
            int row = ty * 4 + i, grow = m * 128 + row;
            if (grow < cnt) {
                float* hrow = g_h + ((size_t)e * T_TOK + grow) * I_DIM + n0 + nh * 128 + tx * 8;
#pragma unroll
                for (int j = 0; j < 8; j++) {
                    float a = a1[i][j];
                    hrow[j] = to_tf32((a / (1.f + expf(-a))) * a3[i][j]);
                }
            }
        }
    }
#endif
}

// ---------------- grouped GEMM2 (g_h @ w2t, weighted scatter) ----------------
// cluster(2): pair covers 256 slots x 512 H-cols (two N=256 accumulators)
__global__ void __launch_bounds__(NT, 1) __cluster_dims__(2, 1, 1)
k_gemm2(float* __restrict__ out) {
#if HAS_TC
    int e = blockIdx.z, nt = blockIdx.y;
    int mp = blockIdx.x >> 1;
    int cnt = g_count[e];
    if (mp * 256 >= cnt) return;
    uint32_t rank = ctarank();

    extern __shared__ char smem[];
    uint32_t sb = smem_u32(smem);
    int tid = threadIdx.x, wid = tid >> 5, lid = tid & 31;

    if (wid == 0) TCGEN05_ALLOC_CG2(sb, 512);
    if (tid == 0) {
#pragma unroll
        for (int s = 0; s < NSTG; s++) {
            MBARRIER_INIT(sb + 16 + 8 * s, 2);
            MBARRIER_INIT(sb + 48 + 8 * s, 1);
        }
    }
    __syncthreads();
    uint32_t tmem;
    asm volatile("ld.shared.b32 %0, [%1];" : "=r"(tmem) : "r"(sb));
    CLUSTER_SYNC();

    int n0 = nt * 512;
    const float* Ab = g_h   + ((size_t)e * T_TOK + (size_t)mp * 256 + rank * 128) * I_DIM;
    const float* Bb = g_w2t + ((size_t)e * H_DIM + n0 + rank * 128) * I_DIM;

    auto issue = [&](int st, int kc) {
        uint32_t base = sb + S_BUF + st * STGB;
        int ko = kc * 32;
#pragma unroll
        for (int j = 0; j < 2; j++) {             // A: own 128 rows
            int idx = tid + NT * j;
            int r = idx >> 3, c4 = idx & 7;
            cpa16(base + SW128(r * 128 + c4 * 16), Ab + (size_t)r * I_DIM + ko + c4 * 4);
        }
#pragma unroll
        for (int j = 0; j < 4; j++) {             // B: 256 rows (2 halves of 2 accs)
            int idx = tid + NT * j;
            int n2 = idx >> 3, c4 = idx & 7;
            // n2<128 -> acc0 half (global n0+rank*128+n2); n2>=128 -> acc1 half (+256)
            cpa16(base + 16384 + SW128(n2 * 128 + c4 * 16),
                  Bb + (size_t)(n2 + (n2 & 128)) * I_DIM + ko + c4 * 4);
        }
        CP_COMMIT();
    };

    issue(0, 0); issue(1, 1); issue(2, 2); issue(3, 3);

    const int NK = I_DIM / 32;  // 128
    for (int kc = 0; kc < NK; kc++) {
        int s = kc & 3, p = (kc >> 2) & 1;
        if (kc < NK - 3) CP_WAIT3();
        else if (kc == NK - 3) CP_WAIT2();
        else if (kc == NK - 2) CP_WAIT1();
        else CP_WAIT0();
        __syncthreads();
        if (wid == 0 && elect1()) {
            FENCE_ASYNC_ALL();
            ARRIVE_RANK0(sb + 16 + 8 * s);
            if (rank == 0) {
                MBARRIER_WAIT_PARITY(sb + 16 + 8 * s, p);
                TCGEN05_FENCE_AFTER();
                uint32_t base = sb + S_BUF + s * STGB;
                uint64_t ad    = mkdesc(base);
                uint64_t bd_lo = mkdesc(base + 16384);
                uint64_t bd_hi = mkdesc(base + 32768);
#pragma unroll
                for (int st4 = 0; st4 < 4; st4++) {
                    uint32_t en = (kc > 0 || st4 > 0) ? 1u : 0u;
                    mma2_tf32(tmem,       ad + st4 * 2, bd_lo + st4 * 2, en);
                    mma2_tf32(tmem + 256, ad + st4 * 2, bd_hi + st4 * 2, en);
                }
                TCGEN05_COMMIT_MCAST2(sb + 48 + 8 * s);
            }
        }
        if (kc + 4 < NK) {
            MBARRIER_WAIT_PARITY(sb + 48 + 8 * s, p);
            issue(s, kc + 4);
        }
    }
#pragma unroll
    for (int s2 = 0; s2 < NSTG; s2++) {
        int kcl = NK - 4 + s2;
        MBARRIER_WAIT_PARITY(sb + 48 + 8 * (kcl & 3), (kcl >> 2) & 1);
    }
    TCGEN05_FENCE_AFTER();

    // epilogue: weighted atomic scatter (own 128 lanes, 512 cols contiguous TMEM)
    int row = (wid & 3) * 32 + lid;
    int slot = mp * 256 + rank * 128 + row;
    bool act = slot < cnt;
    int tok = act ? g_tok[e * T_TOK + slot] : 0;
    float wt = act ? g_wt[e * T_TOK + slot] : 0.f;
    int c0 = (wid >> 2) * 128;
    float* orow = out + (size_t)tok * H_DIM + n0;
#pragma unroll 1
    for (int cb = 0; cb < 128; cb += 32) {
        uint32_t r[32];
        TCGEN05_LD_32X32B_X32(r, tmem + c0 + cb);
        TCGEN05_WAIT_LD();
        if (act) {
#pragma unroll
            for (int q = 0; q < 32; q++)
                atomicAdd(&orow[c0 + cb + q], wt * __uint_as_float(r[q]));
        }
    }
    __syncthreads();
    if (tid == 0)
#pragma unroll
        for (int s = 0; s < NSTG; s++) {
            MBARRIER_INVAL(sb + 16 + 8 * s);
            MBARRIER_INVAL(sb + 48 + 8 * s);
        }
    __syncthreads();
    CLUSTER_SYNC();
    if (wid == 0) { TCGEN05_RELINQ_CG2(); TCGEN05_DEALLOC_CG2(tmem, 512); }
    CLUSTER_SYNC();
#else
    // ---------- FFMA fallback ----------
    int e = blockIdx.z, nt = blockIdx.y, m = blockIdx.x;
    int cnt = g_count[e];
    if (m * 128 >= cnt) return;
    extern __shared__ char smem[];
    float* As = (float*)smem;
    float* Bs = As + 2048;
    int tid = threadIdx.x;
    int tx = tid & 15, ty = tid >> 4;
    int n0 = nt * 512;
    const float* Ab = g_h + ((size_t)e * T_TOK + (size_t)m * 128) * I_DIM;
    for (int nh = 0; nh < 4; nh++) {
        float acc[4][8];
#pragma unroll
        for (int i = 0; i < 4; i++)
#pragma unroll
            for (int j = 0; j < 8; j++) acc[i][j] = 0.f;
        for (int kc = 0; kc < I_DIM / 16; kc++) {
            __syncthreads();
#pragma unroll
            for (int L = 0; L < 4; L++) {
                int f = tid + NT * L;
                int row = f >> 4, k = f & 15;
                As[f] = Ab[(size_t)row * I_DIM + kc * 16 + k];
            }
#pragma unroll
            for (int L = 0; L < 4; L++) {
                int f = tid + NT * L;
                int k = f >> 7, c = f & 127;
                Bs[k * 132 + c] = g_w2t[((size_t)e * H_DIM + n0 + nh * 128 + c) * I_DIM + kc * 16 + k];
            }
            __syncthreads();
#pragma unroll
            for (int k = 0; k < 16; k++) {
                float av[4], b[8];
#pragma unroll
                for (int i = 0; i < 4; i++) av[i] = As[(ty * 4 + i) * 16 + k];
#pragma unroll
                for (int j = 0; j < 8; j++) b[j] = Bs[k * 132 + tx * 8 + j];
#pragma unroll
                for (int i = 0; i < 4; i++)
#pragma unroll
                    for (int j = 0; j < 8; j++) acc[i][j] += av[i] * b[j];
            }
        }
#pragma unroll
        for (int i = 0; i < 4; i++) {
            int row = ty * 4 + i, grow = m * 128 + row;
            if (grow < cnt) {
                int tok = g_tok[e * T_TOK + grow];
                float wt = g_wt[e * T_TOK + grow];
                float* orow = out + (size_t)tok * H_DIM + n0 + nh * 128 + tx * 8;
#pragma unroll
                for (int j = 0; j < 8; j++)
                    atomicAdd(&orow[j], wt * acc[i][j]);
            }
        }
    }
#endif
}

// ---------------- launch ----------------
extern "C" void kernel_launch(void* const* d_in, const int* in_sizes, int n_in,
                              void* d_out, int out_size) {
    const float* x  = (const float*)d_in[0];   // hidden_states [T,H]
    const float* gw = (const float*)d_in[1];   // gate_w [H,E]
    const float* w1 = (const float*)d_in[2];   // [E,H,I]
    const float* w3 = (const float*)d_in[3];   // [E,H,I]
    const float* w2 = (const float*)d_in[4];   // [E,I,H]
    float* out = (float*)d_out;

    cudaFuncSetAttribute(k_gemm1, cudaFuncAttributeMaxDynamicSharedMemorySize, SMEM_TOT);
    cudaFuncSetAttribute(k_gemm2, cudaFuncAttributeMaxDynamicSharedMemorySize, SMEM_TOT);

    k_zero<<<T_TOK * H_DIM / 4 / 256, 256>>>(out);
    k_gate<<<T_TOK, 256>>>(x, gw);
    k_tr13<<<dim3(I_DIM / 32, H_DIM / 32, 2 * E_NUM), 256>>>(w1, w3);
    k_tr2 <<<dim3(H_DIM / 32, I_DIM / 32, E_NUM), 256>>>(w2);
    k_pack<<<dim3(T_TOK / 8, E_NUM), 256>>>(x);
    // x-dim: 2-CTA clusters (pairs) over m; pairs of 256 slots
    k_gemm1<<<dim3(T_TOK / 128, I_DIM / 256, E_NUM), NT, SMEM_TOT>>>();
    k_gemm2<<<dim3(T_TOK / 128, H_DIM / 512, E_NUM), NT, SMEM_TOT>>>(out);
}

// round 7
// speedup vs baseline: 1.5769x; 1.5769x over previous
#include <cuda_runtime.h>
#include <cuda_fp16.h>
#include <cstdint>

// ---------------- problem constants ----------------
#define T_TOK 8192          // B*S
#define H_DIM 1024
#define E_NUM 8
#define I_DIM 4096
#define NT 512              // threads per GEMM CTA

// tcgen05 only legal in the sm_103a arch-accelerated pass
#if !defined(__CUDA_ARCH__) || defined(__CUDA_ARCH_FEAT_SM103_ALL)
#define HAS_TC 1
#else
#define HAS_TC 0
#endif

// ---------------- device scratch (static, allocation-free; halves as u16) ----
__device__ int            g_count[E_NUM];
__device__ int            g_tok[E_NUM * T_TOK];
__device__ float          g_wt [E_NUM * T_TOK];
__device__ unsigned short g_h  [268435456];                       // [E*T, I] half
__device__ unsigned short g_xa [(size_t)E_NUM * T_TOK * H_DIM];   // gathered x half
__device__ unsigned short g_w1t[(size_t)E_NUM * I_DIM * H_DIM];   // [E][I][H] half
__device__ unsigned short g_w3t[(size_t)E_NUM * I_DIM * H_DIM];
__device__ unsigned short g_w2t[(size_t)E_NUM * H_DIM * I_DIM];   // [E][H][I] half

#define SW128(x) ((x) ^ (((x) >> 3) & 0x70))

// bit-cast __half2 -> u32 (no such intrinsic in CUDA; do it via __half2raw)
__device__ __forceinline__ uint32_t h2u(__half2 h) {
    __half2_raw r = *reinterpret_cast<__half2_raw*>(&h);
    return (uint32_t)r.x | ((uint32_t)r.y << 16);
}

#if HAS_TC
__device__ __forceinline__ uint32_t smem_u32(const void* p) {
    uint32_t a;
    asm("{ .reg .u64 t; cvta.to.shared.u64 t, %1; cvt.u32.u64 %0, t; }"
        : "=r"(a) : "l"(p));
    return a;
}
__device__ __forceinline__ uint32_t elect1() {
    uint32_t p;
    asm volatile("{ .reg .pred p; elect.sync _|p, 0xFFFFFFFF; selp.b32 %0,1,0,p; }" : "=r"(p));
    return p;
}
__device__ __forceinline__ void cpa16(uint32_t dst, const void* src) {
    asm volatile("cp.async.cg.shared.global [%0], [%1], 16;" :: "r"(dst), "l"(src));
}
#define CP_COMMIT() asm volatile("cp.async.commit_group;" ::: "memory")
#define CP_WAIT1()  asm volatile("cp.async.wait_group 1;" ::: "memory")
#define CP_WAIT0()  asm volatile("cp.async.wait_group 0;" ::: "memory")

// SW128 K-major smem descriptor (Blackwell): layout=2, version=1, SBO=64, LBO=1
static constexpr uint64_t DESC_BASE =
    (2ull << 61) | (1ull << 46) | (64ull << 32) | (1ull << 16);
__device__ __forceinline__ uint64_t mkdesc(uint32_t smem_addr) {
    return DESC_BASE | ((uint64_t)(smem_addr >> 4) & 0x3FFF);
}
// f16 idesc (cg1): D=F32(1<<4), A=FP16(0), B=FP16(0), N=256 (32<<17), M=128 (8<<24)
static constexpr uint32_t IDESC_F16 = (1u << 4) | (32u << 17) | (8u << 24);

__device__ __forceinline__ void mma_f16(uint32_t d_tmem, uint64_t a_desc,
                                        uint64_t b_desc, uint32_t en) {
    asm volatile(
        "{\n\t"
        ".reg .pred p;\n\t"
        "setp.ne.u32 p, %4, 0;\n\t"
        "tcgen05.mma.cta_group::1.kind::f16 [%0], %1, %2, %3, {%5,%5,%5,%5}, p;\n\t"
        "}"
        :: "r"(d_tmem), "l"(a_desc), "l"(b_desc), "r"(IDESC_F16),
           "r"(en), "r"(0u)
        : "memory");
}

#define TCGEN05_ALLOC(a, n) \
    asm volatile("tcgen05.alloc.cta_group::1.sync.aligned.shared::cta.b32 [%0], %1;" \
        :: "r"((uint32_t)(a)), "r"((uint32_t)(n)) : "memory")
#define TCGEN05_RELINQUISH() \
    asm volatile("tcgen05.relinquish_alloc_permit.cta_group::1.sync.aligned;")
#define TCGEN05_DEALLOC(t, n) \
    asm volatile("tcgen05.dealloc.cta_group::1.sync.aligned.b32 %0, %1;" \
        :: "r"(t), "r"((uint32_t)(n)))
#define TCGEN05_COMMIT(mbar) \
    asm volatile("tcgen05.commit.cta_group::1.mbarrier::arrive::one.shared::cluster.b64 [%0];" \
        :: "r"((uint32_t)(mbar)) : "memory")
#define TCGEN05_FENCE_AFTER() \
    asm volatile("tcgen05.fence::after_thread_sync;" ::: "memory")
#define TCGEN05_WAIT_LD() \
    asm volatile("tcgen05.wait::ld.sync.aligned;" ::: "memory")
#define FENCE_ASYNC() \
    asm volatile("fence.proxy.async.shared::cta;" ::: "memory")

#define MBARRIER_INIT(a, c) \
    asm volatile("mbarrier.init.shared.b64 [%0], %1;" \
        :: "r"((uint32_t)(a)), "r"((uint32_t)(c)) : "memory")
#define MBARRIER_INVAL(a) \
    asm volatile("mbarrier.inval.shared.b64 [%0];" \
        :: "r"((uint32_t)(a)) : "memory")

#define MBARRIER_WAIT_PARITY(mbar_smem_addr, phase_parity) do { \
    uint32_t _mbar = (uint32_t)(mbar_smem_addr); \
    uint32_t _parity = (uint32_t)(phase_parity); \
    uint32_t _done; \
    asm volatile( \
        "{\n\t" \
        ".reg .pred p;\n\t" \
        "mbarrier.try_wait.parity.acquire.cta.shared::cta.b64 p, [%1], %2;\n\t" \
        "selp.b32 %0, 1, 0, p;\n\t" \
        "}" \
        : "=r"(_done) : "r"(_mbar), "r"(_parity) : "memory"); \
    if (!_done) { \
        asm volatile( \
            "{\n\t" \
            ".reg .pred P1;\n\t" \
            "WAIT_LOOP_%=:\n\t" \
            "mbarrier.try_wait.parity.acquire.cta.shared::cta.b64 P1, [%0], %1, 0x989680;\n\t" \
            "@P1 bra.uni WAIT_DONE_%=;\n\t" \
            "bra.uni WAIT_LOOP_%=;\n\t" \
            "WAIT_DONE_%=:\n\t" \
            "}" \
            :: "r"(_mbar), "r"(_parity) : "memory"); \
    } \
} while (0)

#define TCGEN05_LD_32X32B_X32(r, tmem_addr) \
    asm volatile( \
        "tcgen05.ld.sync.aligned.32x32b.x32.b32 " \
        "{%0, %1, %2, %3, %4, %5, %6, %7, " \
        " %8, %9, %10, %11, %12, %13, %14, %15, " \
        " %16, %17, %18, %19, %20, %21, %22, %23, " \
        " %24, %25, %26, %27, %28, %29, %30, %31}, [%32];" \
        : "=r"((r)[0]),  "=r"((r)[1]),  "=r"((r)[2]),  "=r"((r)[3]), \
          "=r"((r)[4]),  "=r"((r)[5]),  "=r"((r)[6]),  "=r"((r)[7]), \
          "=r"((r)[8]),  "=r"((r)[9]),  "=r"((r)[10]), "=r"((r)[11]), \
          "=r"((r)[12]), "=r"((r)[13]), "=r"((r)[14]), "=r"((r)[15]), \
          "=r"((r)[16]), "=r"((r)[17]), "=r"((r)[18]), "=r"((r)[19]), \
          "=r"((r)[20]), "=r"((r)[21]), "=r"((r)[22]), "=r"((r)[23]), \
          "=r"((r)[24]), "=r"((r)[25]), "=r"((r)[26]), "=r"((r)[27]), \
          "=r"((r)[28]), "=r"((r)[29]), "=r"((r)[30]), "=r"((r)[31]) \
        : "r"(tmem_addr))
#endif  // HAS_TC

// ---------------- kernel 0: zero out + counters ----------------
__global__ void k_zero(float* __restrict__ out) {
    size_t i = (size_t)blockIdx.x * blockDim.x + threadIdx.x;
    float4* o4 = (float4*)out;
    if (i < (size_t)T_TOK * H_DIM / 4) o4[i] = make_float4(0.f, 0.f, 0.f, 0.f);
    if (blockIdx.x == 0 && threadIdx.x < E_NUM) g_count[threadIdx.x] = 0;
}

// ---------------- kernel 1: gating (softmax top-2, routing lists) ----------------
__global__ void k_gate(const float* __restrict__ x, const float* __restrict__ gw) {
    int t = blockIdx.x;
    const float* xr = x + (size_t)t * H_DIM;
    float acc[E_NUM];
#pragma unroll
    for (int e = 0; e < E_NUM; e++) acc[e] = 0.f;
    for (int h = threadIdx.x; h < H_DIM; h += 256) {
        float xv = xr[h];
        const float* g = gw + h * E_NUM;
#pragma unroll
        for (int e = 0; e < E_NUM; e++) acc[e] += xv * g[e];
    }
#pragma unroll
    for (int e = 0; e < E_NUM; e++)
#pragma unroll
        for (int off = 16; off > 0; off >>= 1)
            acc[e] += __shfl_xor_sync(0xFFFFFFFF, acc[e], off);
    __shared__ float red[8][E_NUM];
    int wid = threadIdx.x >> 5, lid = threadIdx.x & 31;
    if (lid == 0)
#pragma unroll
        for (int e = 0; e < E_NUM; e++) red[wid][e] = acc[e];
    __syncthreads();
    if (threadIdx.x == 0) {
        float l[E_NUM];
#pragma unroll
        for (int e = 0; e < E_NUM; e++) {
            float s = 0.f;
#pragma unroll
            for (int w = 0; w < 8; w++) s += red[w][e];
            l[e] = s;
        }
        int i1 = 0;
#pragma unroll
        for (int e = 1; e < E_NUM; e++) if (l[e] > l[i1]) i1 = e;
        int i2 = (i1 == 0) ? 1 : 0;
#pragma unroll
        for (int e = 0; e < E_NUM; e++) if (e != i1 && l[e] > l[i2]) i2 = e;
        float e2 = expf(l[i2] - l[i1]);
        float wa = 1.f / (1.f + e2);
        float wb = 1.f - wa;
        int p1 = atomicAdd(&g_count[i1], 1);
        g_tok[i1 * T_TOK + p1] = t;  g_wt[i1 * T_TOK + p1] = wa;
        int p2 = atomicAdd(&g_count[i2], 1);
        g_tok[i2 * T_TOK + p2] = t;  g_wt[i2 * T_TOK + p2] = wb;
    }
}

// ---------------- prep: transpose + fp16-convert weights ----------------
__global__ void k_tr13(const float* __restrict__ w1, const float* __restrict__ w3) {
    __shared__ float tile[32][33];
    int e = blockIdx.z & 7;
    const float* src = (blockIdx.z < E_NUM ? w1 : w3) + (size_t)e * H_DIM * I_DIM;
    unsigned short* dst = (blockIdx.z < E_NUM ? g_w1t : g_w3t) + (size_t)e * I_DIM * H_DIM;
    int i0 = blockIdx.x * 32, h0 = blockIdx.y * 32;
    int tx = threadIdx.x & 31, ty = threadIdx.x >> 5;
#pragma unroll
    for (int r = 0; r < 32; r += 8)
        tile[ty + r][tx] = src[(size_t)(h0 + ty + r) * I_DIM + i0 + tx];
    __syncthreads();
#pragma unroll
    for (int r = 0; r < 32; r += 8)
        dst[(size_t)(i0 + ty + r) * H_DIM + h0 + tx] =
            __half_as_ushort(__float2half_rn(tile[tx][ty + r]));
}
__global__ void k_tr2(const float* __restrict__ w2) {
    __shared__ float tile[32][33];
    int e = blockIdx.z;
    const float* src = w2 + (size_t)e * I_DIM * H_DIM;
    unsigned short* dst = g_w2t + (size_t)e * H_DIM * I_DIM;
    int h0 = blockIdx.x * 32, i0 = blockIdx.y * 32;
    int tx = threadIdx.x & 31, ty = threadIdx.x >> 5;
#pragma unroll
    for (int r = 0; r < 32; r += 8)
        tile[ty + r][tx] = src[(size_t)(i0 + ty + r) * H_DIM + h0 + tx];
    __syncthreads();
#pragma unroll
    for (int r = 0; r < 32; r += 8)
        dst[(size_t)(h0 + ty + r) * I_DIM + i0 + tx] =
            __half_as_ushort(__float2half_rn(tile[tx][ty + r]));
}

// ---------------- pack: gather + fp16-round x rows per expert slot ----------------
__global__ void k_pack(const float* __restrict__ x) {
    int e = blockIdx.y;
    int cnt = g_count[e];
    int slot = blockIdx.x * 8 + (threadIdx.x >> 5);
    int c = threadIdx.x & 31;
    if (slot >= cnt) return;
    int tok = g_tok[e * T_TOK + slot];
    const float4* src = (const float4*)(x + (size_t)tok * H_DIM);
    uint2* dst = (uint2*)(g_xa + ((size_t)e * T_TOK + slot) * H_DIM);
#pragma unroll
    for (int j = 0; j < 8; j++) {
        float4 v = src[c + 32 * j];
        dst[c + 32 * j] = make_uint2(h2u(__floats2half2_rn(v.x, v.y)),
                                     h2u(__floats2half2_rn(v.z, v.w)));
    }
}

// ---------------- GEMM geometry (f16 cg1) ----------------
// K-chunk = 64 halves (128B rows, SW128); 4 f16 K=16 MMA steps per chunk.
// 2-stage cp.async pipeline; stage 80KB.
#define S_MB    16
#define S1_BUF  1024
#define STG     81920
#define S_SMEM  (S1_BUF + 2 * STG)     // 164864
#define S2_TOKS 64
#define S2_WTS  576
#define S2_BUF  2048
#define S2_SMEM (S2_BUF + 2 * STG)     // 165888

// ---------------- grouped GEMM1 (xa@w1t, xa@w3t, SwiGLU -> g_h half) ---------
// M=128 slots, N=256 I-cols (dual accumulator d1/d3 = 512 TMEM cols)
__global__ void __launch_bounds__(NT, 1)
k_gemm1() {
#if HAS_TC
    int e = blockIdx.z, nt = blockIdx.y, m = blockIdx.x;
    int cnt = g_count[e];
    if (m * 128 >= cnt) return;

    extern __shared__ char smem[];
    uint32_t sb = smem_u32(smem);
    int tid = threadIdx.x, wid = tid >> 5, lid = tid & 31;

    if (wid == 0) { TCGEN05_ALLOC(sb, 512); TCGEN05_RELINQUISH(); }
    if (tid == 0) { MBARRIER_INIT(sb + S_MB, 1); MBARRIER_INIT(sb + S_MB + 8, 1); }
    __syncthreads();
    uint32_t tmem;
    asm volatile("ld.shared.b32 %0, [%1];" : "=r"(tmem) : "r"(sb));

    int n0 = nt * 256;
    const unsigned short* Ab  = g_xa  + ((size_t)e * T_TOK + (size_t)m * 128) * H_DIM;
    const unsigned short* B1b = g_w1t + ((size_t)e * I_DIM + n0) * H_DIM;
    const unsigned short* B3b = g_w3t + ((size_t)e * I_DIM + n0) * H_DIM;

    auto issue = [&](int st, int kc) {
        uint32_t sA  = sb + S1_BUF + st * STG;
        uint32_t sB1 = sA + 16384;
        uint32_t sB3 = sB1 + 32768;
        int ko = kc * 64;                                   // halves
#pragma unroll
        for (int j = 0; j < 2; j++) {                       // A: 1024 16B chunks
            int idx = tid + NT * j;
            int row = idx >> 3, c4 = idx & 7;
            cpa16(sA + SW128(row * 128 + c4 * 16), Ab + (size_t)row * H_DIM + ko + c4 * 8);
        }
#pragma unroll
        for (int j = 0; j < 4; j++) {                       // B1,B3: 2048 chunks each
            int idx = tid + NT * j;
            int n = idx >> 3, c4 = idx & 7;
            cpa16(sB1 + SW128(n * 128 + c4 * 16), B1b + (size_t)n * H_DIM + ko + c4 * 8);
            cpa16(sB3 + SW128(n * 128 + c4 * 16), B3b + (size_t)n * H_DIM + ko + c4 * 8);
        }
        CP_COMMIT();
    };

    issue(0, 0);
    issue(1, 1);

    const int NK = H_DIM / 64;  // 16
    int ph0 = 0, ph1 = 0;
    for (int kc = 0; kc < NK; kc++) {
        int st = kc & 1;
        if (kc + 2 < NK) CP_WAIT1(); else CP_WAIT0();
        __syncthreads();
        if (wid == 0 && elect1()) {
            FENCE_ASYNC();
            uint32_t base = sb + S1_BUF + st * STG;
            uint64_t ad  = mkdesc(base);
            uint64_t bd1 = mkdesc(base + 16384);
            uint64_t bd3 = mkdesc(base + 49152);
#pragma unroll
            for (int s = 0; s < 4; s++) {                   // 4 x K=16
                uint32_t en = (kc > 0 || s > 0) ? 1u : 0u;
                mma_f16(tmem,       ad + s * 2, bd1 + s * 2, en);
                mma_f16(tmem + 256, ad + s * 2, bd3 + s * 2, en);
            }
            TCGEN05_COMMIT(sb + S_MB + 8 * st);
        }
        if (kc + 2 < NK) {
            if (st == 0) { MBARRIER_WAIT_PARITY(sb + S_MB,     ph0); ph0 ^= 1; }
            else         { MBARRIER_WAIT_PARITY(sb + S_MB + 8, ph1); ph1 ^= 1; }
            issue(st, kc + 2);
        }
    }
    MBARRIER_WAIT_PARITY(sb + S_MB,     ph0);
    MBARRIER_WAIT_PARITY(sb + S_MB + 8, ph1);
    TCGEN05_FENCE_AFTER();

    // epilogue: silu(d1)*d3 -> half -> g_h
    int row = (wid & 3) * 32 + lid;
    int grow = m * 128 + row;
    bool act = grow < cnt;
    int c0 = (wid >> 2) * 64;
    unsigned short* hrow = g_h + ((size_t)e * T_TOK + grow) * I_DIM + n0;
#pragma unroll 1
    for (int cb = 0; cb < 64; cb += 32) {
        uint32_t ra[32], rb[32];
        TCGEN05_LD_32X32B_X32(ra, tmem + c0 + cb);
        TCGEN05_LD_32X32B_X32(rb, tmem + 256 + c0 + cb);
        TCGEN05_WAIT_LD();
        if (act) {
#pragma unroll
            for (int q = 0; q < 32; q += 4) {
                float o[4];
#pragma unroll
                for (int u = 0; u < 4; u++) {
                    float a = __uint_as_float(ra[q + u]);
                    float b = __uint_as_float(rb[q + u]);
                    o[u] = (a / (1.0f + expf(-a))) * b;
                }
                *(uint2*)(hrow + c0 + cb + q) =
                    make_uint2(h2u(__floats2half2_rn(o[0], o[1])),
                               h2u(__floats2half2_rn(o[2], o[3])));
            }
        }
    }
    __syncthreads();
    if (tid == 0) { MBARRIER_INVAL(sb + S_MB); MBARRIER_INVAL(sb + S_MB + 8); }
    __syncthreads();
    if (wid == 0) TCGEN05_DEALLOC(tmem, 512);
#else
    // ---------- FFMA fallback (plain sm_103 pass) ----------
    int e = blockIdx.z, nt = blockIdx.y, m = blockIdx.x;
    int cnt = g_count[e];
    if (m * 128 >= cnt) return;
    extern __shared__ char smem[];
    float* As  = (float*)smem;
    float* B1s = As + 2048;
    float* B3s = B1s + 16 * 132;
    int tid = threadIdx.x;
    int tx = tid & 15, ty = tid >> 4;
    int n0 = nt * 256;
    const unsigned short* Ab = g_xa + ((size_t)e * T_TOK + (size_t)m * 128) * H_DIM;
    for (int nh = 0; nh < 2; nh++) {
        float a1[4][8], a3[4][8];
#pragma unroll
        for (int i = 0; i < 4; i++)
#pragma unroll
            for (int j = 0; j < 8; j++) { a1[i][j] = 0.f; a3[i][j] = 0.f; }
        for (int kc = 0; kc < H_DIM / 16; kc++) {
            __syncthreads();
#pragma unroll
            for (int L = 0; L < 4; L++) {
                int f = tid + NT * L;
                int row = f >> 4, k = f & 15;
                As[f] = __half2float(__ushort_as_half(Ab[(size_t)row * H_DIM + kc * 16 + k]));
            }
#pragma unroll
            for (int L = 0; L < 4; L++) {
                int f = tid + NT * L;
                int k = f >> 7, c = f & 127;
                B1s[k * 132 + c] = __half2float(__ushort_as_half(
                    g_w1t[((size_t)e * I_DIM + n0 + nh * 128 + c) * H_DIM + kc * 16 + k]));
                B3s[k * 132 + c] = __half2float(__ushort_as_half(
                    g_w3t[((size_t)e * I_DIM + n0 + nh * 128 + c) * H_DIM + kc * 16 + k]));
            }
            __syncthreads();
#pragma unroll
            for (int k = 0; k < 16; k++) {
                float av[4], b1[8], b3[8];
#pragma unroll
                for (int i = 0; i < 4; i++) av[i] = As[(ty * 4 + i) * 16 + k];
#pragma unroll
                for (int j = 0; j < 8; j++) {
                    b1[j] = B1s[k * 132 + tx * 8 + j];
                    b3[j] = B3s[k * 132 + tx * 8 + j];
                }
#pragma unroll
                for (int i = 0; i < 4; i++)
#pragma unroll
                    for (int j = 0; j < 8; j++) {
                        a1[i][j] += av[i] * b1[j];
                        a3[i][j] += av[i] * b3[j];
                    }
            }
        }
#pragma unroll
        for (int i = 0; i < 4; i++) {
            int row = ty * 4 + i, grow = m * 128 + row;
            if (grow < cnt) {
                unsigned short* hrow = g_h + ((size_t)e * T_TOK + grow) * I_DIM + n0 + nh * 128 + tx * 8;
#pragma unroll
                for (int j = 0; j < 8; j++) {
                    float a = a1[i][j];
                    hrow[j] = __half_as_ushort(__float2half_rn((a / (1.f + expf(-a))) * a3[i][j]));
                }
            }
        }
    }
#endif
}

// ---------------- grouped GEMM2 (g_h @ w2t, weighted scatter) ----------------
// M=128, N=512 (two N=256 accumulators = 512 TMEM cols)
__global__ void __launch_bounds__(NT, 1)
k_gemm2(float* __restrict__ out) {
#if HAS_TC
    int e = blockIdx.z, nt = blockIdx.y, m = blockIdx.x;
    int cnt = g_count[e];
    if (m * 128 >= cnt) return;

    extern __shared__ char smem[];
    uint32_t sb = smem_u32(smem);
    int tid = threadIdx.x, wid = tid >> 5, lid = tid & 31;

    if (tid < 128) {
        int r = m * 128 + tid;
        bool a = r < cnt;
        ((int*)(smem + S2_TOKS))[tid]  = a ? g_tok[e * T_TOK + r] : 0;
        ((float*)(smem + S2_WTS))[tid] = a ? g_wt[e * T_TOK + r] : 0.f;
    }
    if (wid == 0) { TCGEN05_ALLOC(sb, 512); TCGEN05_RELINQUISH(); }
    if (tid == 0) { MBARRIER_INIT(sb + S_MB, 1); MBARRIER_INIT(sb + S_MB + 8, 1); }
    __syncthreads();
    uint32_t tmem;
    asm volatile("ld.shared.b32 %0, [%1];" : "=r"(tmem) : "r"(sb));

    int n0 = nt * 512;
    const unsigned short* Ab = g_h   + ((size_t)e * T_TOK + (size_t)m * 128) * I_DIM;
    const unsigned short* Bb = g_w2t + ((size_t)e * H_DIM + n0) * I_DIM;

    auto issue = [&](int st, int kc) {
        uint32_t sA = sb + S2_BUF + st * STG;
        uint32_t sB = sA + 16384;
        int ko = kc * 64;
#pragma unroll
        for (int j = 0; j < 2; j++) {                       // A: 1024 chunks
            int idx = tid + NT * j;
            int row = idx >> 3, c4 = idx & 7;
            cpa16(sA + SW128(row * 128 + c4 * 16), Ab + (size_t)row * I_DIM + ko + c4 * 8);
        }
#pragma unroll
        for (int j = 0; j < 8; j++) {                       // B: 512 rows = 4096 chunks
            int idx = tid + NT * j;
            int n = idx >> 3, c4 = idx & 7;
            cpa16(sB + SW128(n * 128 + c4 * 16), Bb + (size_t)n * I_DIM + ko + c4 * 8);
        }
        CP_COMMIT();
    };

    issue(0, 0);
    issue(1, 1);

    const int NK = I_DIM / 64;  // 64
    int ph0 = 0, ph1 = 0;
    for (int kc = 0; kc < NK; kc++) {
        int st = kc & 1;
        if (kc + 2 < NK) CP_WAIT1(); else CP_WAIT0();
        __syncthreads();
        if (wid == 0 && elect1()) {
            FENCE_ASYNC();
            uint32_t base = sb + S2_BUF + st * STG;
            uint64_t ad    = mkdesc(base);
            uint64_t bd_lo = mkdesc(base + 16384);
            uint64_t bd_hi = mkdesc(base + 16384 + 32768);
#pragma unroll
            for (int s = 0; s < 4; s++) {
                uint32_t en = (kc > 0 || s > 0) ? 1u : 0u;
                mma_f16(tmem,       ad + s * 2, bd_lo + s * 2, en);
                mma_f16(tmem + 256, ad + s * 2, bd_hi + s * 2, en);
            }
            TCGEN05_COMMIT(sb + S_MB + 8 * st);
        }
        if (kc + 2 < NK) {
            if (st == 0) { MBARRIER_WAIT_PARITY(sb + S_MB,     ph0); ph0 ^= 1; }
            else         { MBARRIER_WAIT_PARITY(sb + S_MB + 8, ph1); ph1 ^= 1; }
            issue(st, kc + 2);
        }
    }
    MBARRIER_WAIT_PARITY(sb + S_MB,     ph0);
    MBARRIER_WAIT_PARITY(sb + S_MB + 8, ph1);
    TCGEN05_FENCE_AFTER();

    // epilogue: weighted atomic scatter; 512 cols via 4 warpgroups x 128 cols
    int row = (wid & 3) * 32 + lid;
    int grow = m * 128 + row;
    bool act = grow < cnt;
    int tok = ((const int*)(smem + S2_TOKS))[row];
    float wt = ((const float*)(smem + S2_WTS))[row];
    int c0 = (wid >> 2) * 128;
    float* orow = out + (size_t)tok * H_DIM + n0;
#pragma unroll 1
    for (int cb = 0; cb < 128; cb += 32) {
        uint32_t r[32];
        uint32_t taddr = (c0 + cb < 256) ? (tmem + c0 + cb) : (tmem + 256 + (c0 + cb - 256));
        TCGEN05_LD_32X32B_X32(r, taddr);
        TCGEN05_WAIT_LD();
        if (act) {
#pragma unroll
            for (int q = 0; q < 32; q++)
                atomicAdd(&orow[c0 + cb + q], wt * __uint_as_float(r[q]));
        }
    }
    __syncthreads();
    if (tid == 0) { MBARRIER_INVAL(sb + S_MB); MBARRIER_INVAL(sb + S_MB + 8); }
    __syncthreads();
    if (wid == 0) TCGEN05_DEALLOC(tmem, 512);
#else
    // ---------- FFMA fallback ----------
    int e = blockIdx.z, nt = blockIdx.y, m = blockIdx.x;
    int cnt = g_count[e];
    if (m * 128 >= cnt) return;
    extern __shared__ char smem[];
    float* As = (float*)smem;
    float* Bs = As + 2048;
    int tid = threadIdx.x;
    int tx = tid & 15, ty = tid >> 4;
    int n0 = nt * 512;
    const unsigned short* Ab = g_h + ((size_t)e * T_TOK + (size_t)m * 128) * I_DIM;
    for (int nh = 0; nh < 4; nh++) {
        float acc[4][8];
#pragma unroll
        for (int i = 0; i < 4; i++)
#pragma unroll
            for (int j = 0; j < 8; j++) acc[i][j] = 0.f;
        for (int kc = 0; kc < I_DIM / 16; kc++) {
            __syncthreads();
#pragma unroll
            for (int L = 0; L < 4; L++) {
                int f = tid + NT * L;
                int row = f >> 4, k = f & 15;
                As[f] = __half2float(__ushort_as_half(Ab[(size_t)row * I_DIM + kc * 16 + k]));
            }
#pragma unroll
            for (int L = 0; L < 4; L++) {
                int f = tid + NT * L;
                int k = f >> 7, c = f & 127;
                Bs[k * 132 + c] = __half2float(__ushort_as_half(
                    g_w2t[((size_t)e * H_DIM + n0 + nh * 128 + c) * I_DIM + kc * 16 + k]));
            }
            __syncthreads();
#pragma unroll
            for (int k = 0; k < 16; k++) {
                float av[4], b[8];
#pragma unroll
                for (int i = 0; i < 4; i++) av[i] = As[(ty * 4 + i) * 16 + k];
#pragma unroll
                for (int j = 0; j < 8; j++) b[j] = Bs[k * 132 + tx * 8 + j];
#pragma unroll
                for (int i = 0; i < 4; i++)
#pragma unroll
                    for (int j = 0; j < 8; j++) acc[i][j] += av[i] * b[j];
            }
        }
#pragma unroll
        for (int i = 0; i < 4; i++) {
            int row = ty * 4 + i, grow = m * 128 + row;
            if (grow < cnt) {
                int tok = g_tok[e * T_TOK + grow];
                float wt = g_wt[e * T_TOK + grow];
                float* orow = out + (size_t)tok * H_DIM + n0 + nh * 128 + tx * 8;
#pragma unroll
                for (int j = 0; j < 8; j++)
                    atomicAdd(&orow[j], wt * acc[i][j]);
            }
        }
    }
#endif
}

// ---------------- launch ----------------
extern "C" void kernel_launch(void* const* d_in, const int* in_sizes, int n_in,
                              void* d_out, int out_size) {
    const float* x  = (const float*)d_in[0];   // hidden_states [T,H]
    const float* gw = (const float*)d_in[1];   // gate_w [H,E]
    const float* w1 = (const float*)d_in[2];   // [E,H,I]
    const float* w3 = (const float*)d_in[3];   // [E,H,I]
    const float* w2 = (const float*)d_in[4];   // [E,I,H]
    float* out = (float*)d_out;

    cudaFuncSetAttribute(k_gemm1, cudaFuncAttributeMaxDynamicSharedMemorySize, S_SMEM);
    cudaFuncSetAttribute(k_gemm2, cudaFuncAttributeMaxDynamicSharedMemorySize, S2_SMEM);

    k_zero<<<T_TOK * H_DIM / 4 / 256, 256>>>(out);
    k_gate<<<T_TOK, 256>>>(x, gw);
    k_tr13<<<dim3(I_DIM / 32, H_DIM / 32, 2 * E_NUM), 256>>>(w1, w3);
    k_tr2 <<<dim3(H_DIM / 32, I_DIM / 32, E_NUM), 256>>>(w2);
    k_pack<<<dim3(T_TOK / 8, E_NUM), 256>>>(x);
    // grid.x = m-slot (fastest -> co-resident CTAs share (e,n) B stream in L2)
    k_gemm1<<<dim3(T_TOK / 128, I_DIM / 256, E_NUM), NT, S_SMEM>>>();
    k_gemm2<<<dim3(T_TOK / 128, H_DIM / 512, E_NUM), NT, S2_SMEM>>>(out);
}

// round 8
// speedup vs baseline: 2.3451x; 1.4872x over previous
#include <cuda_runtime.h>
#include <cuda_fp16.h>
#include <cstdint>

// ---------------- problem constants ----------------
#define T_TOK 8192          // B*S
#define H_DIM 1024
#define E_NUM 8
#define I_DIM 4096
#define NT 512              // threads per GEMM CTA

// tcgen05 only legal in the sm_103a arch-accelerated pass
#if !defined(__CUDA_ARCH__) || defined(__CUDA_ARCH_FEAT_SM103_ALL)
#define HAS_TC 1
#else
#define HAS_TC 0
#endif

// ---------------- device scratch (static, allocation-free; halves as u16) ----
__device__ int            g_count[E_NUM];
__device__ int            g_tok[E_NUM * T_TOK];
__device__ float          g_wt [E_NUM * T_TOK];
__device__ unsigned short g_h  [268435456];                       // [E*T, I] half
__device__ unsigned short g_xa [(size_t)E_NUM * T_TOK * H_DIM];   // gathered x half
__device__ unsigned short g_w1t[(size_t)E_NUM * I_DIM * H_DIM];   // [E][I][H] half
__device__ unsigned short g_w3t[(size_t)E_NUM * I_DIM * H_DIM];
__device__ unsigned short g_w2t[(size_t)E_NUM * H_DIM * I_DIM];   // [E][H][I] half

#define SW64(x) ((x) ^ (((x) >> 3) & 0x30))

// bit-cast __half2 -> u32
__device__ __forceinline__ uint32_t h2u(__half2 h) {
    __half2_raw r = *reinterpret_cast<__half2_raw*>(&h);
    return (uint32_t)r.x | ((uint32_t)r.y << 16);
}

#if HAS_TC
__device__ __forceinline__ uint32_t smem_u32(const void* p) {
    uint32_t a;
    asm("{ .reg .u64 t; cvta.to.shared.u64 t, %1; cvt.u32.u64 %0, t; }"
        : "=r"(a) : "l"(p));
    return a;
}
__device__ __forceinline__ uint32_t elect1() {
    uint32_t p;
    asm volatile("{ .reg .pred p; elect.sync _|p, 0xFFFFFFFF; selp.b32 %0,1,0,p; }" : "=r"(p));
    return p;
}
__device__ __forceinline__ void cpa16(uint32_t dst, const void* src) {
    asm volatile("cp.async.cg.shared.global [%0], [%1], 16;" :: "r"(dst), "l"(src));
}
#define CP_COMMIT() asm volatile("cp.async.commit_group;" ::: "memory")
#define CP_WAIT2()  asm volatile("cp.async.wait_group 2;" ::: "memory")
#define CP_WAIT1()  asm volatile("cp.async.wait_group 1;" ::: "memory")
#define CP_WAIT0()  asm volatile("cp.async.wait_group 0;" ::: "memory")

// SW64 K-major smem descriptor (Blackwell): layout=4, version=1, SBO=32, LBO=1
// (64B rows; atom = 8 rows x 64B = 512B = 32 x 16B units)
static constexpr uint64_t DESC_BASE64 =
    (4ull << 61) | (1ull << 46) | (32ull << 32) | (1ull << 16);
__device__ __forceinline__ uint64_t mkdesc(uint32_t smem_addr) {
    return DESC_BASE64 | ((uint64_t)(smem_addr >> 4) & 0x3FFF);
}
// f16 idesc (cg1): D=F32(1<<4), A=FP16(0), B=FP16(0), N=256 (32<<17), M=128 (8<<24)
static constexpr uint32_t IDESC_F16 = (1u << 4) | (32u << 17) | (8u << 24);

__device__ __forceinline__ void mma_f16(uint32_t d_tmem, uint64_t a_desc,
                                        uint64_t b_desc, uint32_t en) {
    asm volatile(
        "{\n\t"
        ".reg .pred p;\n\t"
        "setp.ne.u32 p, %4, 0;\n\t"
        "tcgen05.mma.cta_group::1.kind::f16 [%0], %1, %2, %3, {%5,%5,%5,%5}, p;\n\t"
        "}"
        :: "r"(d_tmem), "l"(a_desc), "l"(b_desc), "r"(IDESC_F16),
           "r"(en), "r"(0u)
        : "memory");
}

#define TCGEN05_ALLOC(a, n) \
    asm volatile("tcgen05.alloc.cta_group::1.sync.aligned.shared::cta.b32 [%0], %1;" \
        :: "r"((uint32_t)(a)), "r"((uint32_t)(n)) : "memory")
#define TCGEN05_RELINQUISH() \
    asm volatile("tcgen05.relinquish_alloc_permit.cta_group::1.sync.aligned;")
#define TCGEN05_DEALLOC(t, n) \
    asm volatile("tcgen05.dealloc.cta_group::1.sync.aligned.b32 %0, %1;" \
        :: "r"(t), "r"((uint32_t)(n)))
#define TCGEN05_COMMIT(mbar) \
    asm volatile("tcgen05.commit.cta_group::1.mbarrier::arrive::one.shared::cluster.b64 [%0];" \
        :: "r"((uint32_t)(mbar)) : "memory")
#define TCGEN05_FENCE_AFTER() \
    asm volatile("tcgen05.fence::after_thread_sync;" ::: "memory")
#define TCGEN05_WAIT_LD() \
    asm volatile("tcgen05.wait::ld.sync.aligned;" ::: "memory")
#define FENCE_ASYNC() \
    asm volatile("fence.proxy.async.shared::cta;" ::: "memory")

#define MBARRIER_INIT(a, c) \
    asm volatile("mbarrier.init.shared.b64 [%0], %1;" \
        :: "r"((uint32_t)(a)), "r"((uint32_t)(c)) : "memory")
#define MBARRIER_INVAL(a) \
    asm volatile("mbarrier.inval.shared.b64 [%0];" \
        :: "r"((uint32_t)(a)) : "memory")

#define MBARRIER_WAIT_PARITY(mbar_smem_addr, phase_parity) do { \
    uint32_t _mbar = (uint32_t)(mbar_smem_addr); \
    uint32_t _parity = (uint32_t)(phase_parity); \
    uint32_t _done; \
    asm volatile( \
        "{\n\t" \
        ".reg .pred p;\n\t" \
        "mbarrier.try_wait.parity.acquire.cta.shared::cta.b64 p, [%1], %2;\n\t" \
        "selp.b32 %0, 1, 0, p;\n\t" \
        "}" \
        : "=r"(_done) : "r"(_mbar), "r"(_parity) : "memory"); \
    if (!_done) { \
        asm volatile( \
            "{\n\t" \
            ".reg .pred P1;\n\t" \
            "WAIT_LOOP_%=:\n\t" \
            "mbarrier.try_wait.parity.acquire.cta.shared::cta.b64 P1, [%0], %1, 0x989680;\n\t" \
            "@P1 bra.uni WAIT_DONE_%=;\n\t" \
            "bra.uni WAIT_LOOP_%=;\n\t" \
            "WAIT_DONE_%=:\n\t" \
            "}" \
            :: "r"(_mbar), "r"(_parity) : "memory"); \
    } \
} while (0)

#define TCGEN05_LD_32X32B_X32(r, tmem_addr) \
    asm volatile( \
        "tcgen05.ld.sync.aligned.32x32b.x32.b32 " \
        "{%0, %1, %2, %3, %4, %5, %6, %7, " \
        " %8, %9, %10, %11, %12, %13, %14, %15, " \
        " %16, %17, %18, %19, %20, %21, %22, %23, " \
        " %24, %25, %26, %27, %28, %29, %30, %31}, [%32];" \
        : "=r"((r)[0]),  "=r"((r)[1]),  "=r"((r)[2]),  "=r"((r)[3]), \
          "=r"((r)[4]),  "=r"((r)[5]),  "=r"((r)[6]),  "=r"((r)[7]), \
          "=r"((r)[8]),  "=r"((r)[9]),  "=r"((r)[10]), "=r"((r)[11]), \
          "=r"((r)[12]), "=r"((r)[13]), "=r"((r)[14]), "=r"((r)[15]), \
          "=r"((r)[16]), "=r"((r)[17]), "=r"((r)[18]), "=r"((r)[19]), \
          "=r"((r)[20]), "=r"((r)[21]), "=r"((r)[22]), "=r"((r)[23]), \
          "=r"((r)[24]), "=r"((r)[25]), "=r"((r)[26]), "=r"((r)[27]), \
          "=r"((r)[28]), "=r"((r)[29]), "=r"((r)[30]), "=r"((r)[31]) \
        : "r"(tmem_addr))
#endif  // HAS_TC

// ---------------- kernel 0: zero out + counters ----------------
__global__ void k_zero(float* __restrict__ out) {
    size_t i = (size_t)blockIdx.x * blockDim.x + threadIdx.x;
    float4* o4 = (float4*)out;
    if (i < (size_t)T_TOK * H_DIM / 4) o4[i] = make_float4(0.f, 0.f, 0.f, 0.f);
    if (blockIdx.x == 0 && threadIdx.x < E_NUM) g_count[threadIdx.x] = 0;
}

// ---------------- kernel 1: gating (softmax top-2, routing lists) ----------------
__global__ void k_gate(const float* __restrict__ x, const float* __restrict__ gw) {
    int t = blockIdx.x;
    const float* xr = x + (size_t)t * H_DIM;
    float acc[E_NUM];
#pragma unroll
    for (int e = 0; e < E_NUM; e++) acc[e] = 0.f;
    for (int h = threadIdx.x; h < H_DIM; h += 256) {
        float xv = xr[h];
        const float* g = gw + h * E_NUM;
#pragma unroll
        for (int e = 0; e < E_NUM; e++) acc[e] += xv * g[e];
    }
#pragma unroll
    for (int e = 0; e < E_NUM; e++)
#pragma unroll
        for (int off = 16; off > 0; off >>= 1)
            acc[e] += __shfl_xor_sync(0xFFFFFFFF, acc[e], off);
    __shared__ float red[8][E_NUM];
    int wid = threadIdx.x >> 5, lid = threadIdx.x & 31;
    if (lid == 0)
#pragma unroll
        for (int e = 0; e < E_NUM; e++) red[wid][e] = acc[e];
    __syncthreads();
    if (threadIdx.x == 0) {
        float l[E_NUM];
#pragma unroll
        for (int e = 0; e < E_NUM; e++) {
            float s = 0.f;
#pragma unroll
            for (int w = 0; w < 8; w++) s += red[w][e];
            l[e] = s;
        }
        int i1 = 0;
#pragma unroll
        for (int e = 1; e < E_NUM; e++) if (l[e] > l[i1]) i1 = e;
        int i2 = (i1 == 0) ? 1 : 0;
#pragma unroll
        for (int e = 0; e < E_NUM; e++) if (e != i1 && l[e] > l[i2]) i2 = e;
        float e2 = expf(l[i2] - l[i1]);
        float wa = 1.f / (1.f + e2);
        float wb = 1.f - wa;
        int p1 = atomicAdd(&g_count[i1], 1);
        g_tok[i1 * T_TOK + p1] = t;  g_wt[i1 * T_TOK + p1] = wa;
        int p2 = atomicAdd(&g_count[i2], 1);
        g_tok[i2 * T_TOK + p2] = t;  g_wt[i2 * T_TOK + p2] = wb;
    }
}

// ---------------- prep: transpose + fp16-convert weights ----------------
__global__ void k_tr13(const float* __restrict__ w1, const float* __restrict__ w3) {
    __shared__ float tile[32][33];
    int e = blockIdx.z & 7;
    const float* src = (blockIdx.z < E_NUM ? w1 : w3) + (size_t)e * H_DIM * I_DIM;
    unsigned short* dst = (blockIdx.z < E_NUM ? g_w1t : g_w3t) + (size_t)e * I_DIM * H_DIM;
    int i0 = blockIdx.x * 32, h0 = blockIdx.y * 32;
    int tx = threadIdx.x & 31, ty = threadIdx.x >> 5;
#pragma unroll
    for (int r = 0; r < 32; r += 8)
        tile[ty + r][tx] = src[(size_t)(h0 + ty + r) * I_DIM + i0 + tx];
    __syncthreads();
#pragma unroll
    for (int r = 0; r < 32; r += 8)
        dst[(size_t)(i0 + ty + r) * H_DIM + h0 + tx] =
            __half_as_ushort(__float2half_rn(tile[tx][ty + r]));
}
__global__ void k_tr2(const float* __restrict__ w2) {
    __shared__ float tile[32][33];
    int e = blockIdx.z;
    const float* src = w2 + (size_t)e * I_DIM * H_DIM;
    unsigned short* dst = g_w2t + (size_t)e * H_DIM * I_DIM;
    int h0 = blockIdx.x * 32, i0 = blockIdx.y * 32;
    int tx = threadIdx.x & 31, ty = threadIdx.x >> 5;
#pragma unroll
    for (int r = 0; r < 32; r += 8)
        tile[ty + r][tx] = src[(size_t)(i0 + ty + r) * H_DIM + h0 + tx];
    __syncthreads();
#pragma unroll
    for (int r = 0; r < 32; r += 8)
        dst[(size_t)(h0 + ty + r) * I_DIM + i0 + tx] =
            __half_as_ushort(__float2half_rn(tile[tx][ty + r]));
}

// ---------------- pack: gather + fp16-round x rows per expert slot ----------------
__global__ void k_pack(const float* __restrict__ x) {
    int e = blockIdx.y;
    int cnt = g_count[e];
    int slot = blockIdx.x * 8 + (threadIdx.x >> 5);
    int c = threadIdx.x & 31;
    if (slot >= cnt) return;
    int tok = g_tok[e * T_TOK + slot];
    const float4* src = (const float4*)(x + (size_t)tok * H_DIM);
    uint2* dst = (uint2*)(g_xa + ((size_t)e * T_TOK + slot) * H_DIM);
#pragma unroll
    for (int j = 0; j < 8; j++) {
        float4 v = src[c + 32 * j];
        dst[c + 32 * j] = make_uint2(h2u(__floats2half2_rn(v.x, v.y)),
                                     h2u(__floats2half2_rn(v.z, v.w)));
    }
}

// ---------------- GEMM geometry (f16, SW64, 4-stage) ----------------
// K-chunk = 32 halves (64B rows, SW64); 2 f16 K=16 MMA steps per chunk.
// 4-stage cp.async ring, lookahead 3: loads(kc+3) reuse buffer of chunk kc-1.
#define NSTG    4
#define S_MB    16                       // 4 commit mbars at 16,24,32,40
#define S1_BUF  1024
#define STG     40960                    // GEMM1: A 8K + B1 16K + B3 16K
#define S_SMEM  (S1_BUF + NSTG * STG)    // 164864
#define S2_TOKS 64
#define S2_WTS  576
#define S2_BUF  2048
#define S2_SMEM (S2_BUF + NSTG * STG)    // 165888  (GEMM2 stage: A 8K + B 32K)

// ---------------- grouped GEMM1 (xa@w1t, xa@w3t, SwiGLU -> g_h half) ---------
// M=128 slots, N=256 I-cols (dual accumulator d1/d3 = 512 TMEM cols)
__global__ void __launch_bounds__(NT, 1)
k_gemm1() {
#if HAS_TC
    int e = blockIdx.z, nt = blockIdx.y, m = blockIdx.x;
    int cnt = g_count[e];
    if (m * 128 >= cnt) return;

    extern __shared__ char smem[];
    uint32_t sb = smem_u32(smem);
    int tid = threadIdx.x, wid = tid >> 5, lid = tid & 31;

    if (wid == 0) { TCGEN05_ALLOC(sb, 512); TCGEN05_RELINQUISH(); }
    if (tid == 0)
#pragma unroll
        for (int b = 0; b < NSTG; b++) MBARRIER_INIT(sb + S_MB + 8 * b, 1);
    __syncthreads();
    uint32_t tmem;
    asm volatile("ld.shared.b32 %0, [%1];" : "=r"(tmem) : "r"(sb));

    int n0 = nt * 256;
    const unsigned short* Ab  = g_xa  + ((size_t)e * T_TOK + (size_t)m * 128) * H_DIM;
    const unsigned short* B1b = g_w1t + ((size_t)e * I_DIM + n0) * H_DIM;
    const unsigned short* B3b = g_w3t + ((size_t)e * I_DIM + n0) * H_DIM;

    auto issue = [&](int buf, int kc) {
        uint32_t sA  = sb + S1_BUF + buf * STG;
        uint32_t sB1 = sA + 8192;
        uint32_t sB3 = sB1 + 16384;
        int ko = kc * 32;                                   // halves
        {                                                   // A: 512 16B chunks
            int row = tid >> 2, c4 = tid & 3;
            cpa16(sA + SW64(row * 64 + c4 * 16), Ab + (size_t)row * H_DIM + ko + c4 * 8);
        }
#pragma unroll
        for (int j = 0; j < 2; j++) {                       // B1,B3: 1024 chunks each
            int idx = tid + NT * j;
            int n = idx >> 2, c4 = idx & 3;
            cpa16(sB1 + SW64(n * 64 + c4 * 16), B1b + (size_t)n * H_DIM + ko + c4 * 8);
            cpa16(sB3 + SW64(n * 64 + c4 * 16), B3b + (size_t)n * H_DIM + ko + c4 * 8);
        }
        CP_COMMIT();
    };

    issue(0, 0); issue(1, 1); issue(2, 2);

    const int NK = H_DIM / 32;  // 32
    for (int kc = 0; kc < NK; kc++) {
        int buf = kc & 3;
        int rem = NK - 1 - kc;
        if (rem >= 2) CP_WAIT2(); else if (rem == 1) CP_WAIT1(); else CP_WAIT0();
        // buffer-reuse guard for loads(kc+3): wait MMA(kc-1) (one thread)
        if (tid == 0 && kc >= 1 && kc + 3 < NK) {
            int b = (kc + 3) & 3;
            int n = (kc - 1 - b) >> 2;
            MBARRIER_WAIT_PARITY(sb + S_MB + 8 * b, n & 1);
        }
        __syncthreads();
        if (wid == 0 && elect1()) {
            FENCE_ASYNC();
            uint32_t base = sb + S1_BUF + buf * STG;
            uint64_t ad  = mkdesc(base);
            uint64_t bd1 = mkdesc(base + 8192);
            uint64_t bd3 = mkdesc(base + 24576);
#pragma unroll
            for (int s = 0; s < 2; s++) {                   // 2 x K=16
                uint32_t en = (kc > 0 || s > 0) ? 1u : 0u;
                mma_f16(tmem,       ad + s * 2, bd1 + s * 2, en);
                mma_f16(tmem + 256, ad + s * 2, bd3 + s * 2, en);
            }
            TCGEN05_COMMIT(sb + S_MB + 8 * buf);
        }
        if (kc + 3 < NK) issue((kc + 3) & 3, kc + 3);
    }
    {   // final: wait last chunk's commit (in-order completion => all done)
        int bf = (NK - 1) & 3;
        int nf = (NK - 1 - bf) >> 2;
        MBARRIER_WAIT_PARITY(sb + S_MB + 8 * bf, nf & 1);
    }
    TCGEN05_FENCE_AFTER();

    // epilogue: silu(d1)*d3 -> half -> g_h
    int row = (wid & 3) * 32 + lid;
    int grow = m * 128 + row;
    bool act = grow < cnt;
    int c0 = (wid >> 2) * 64;
    unsigned short* hrow = g_h + ((size_t)e * T_TOK + grow) * I_DIM + n0;
#pragma unroll 1
    for (int cb = 0; cb < 64; cb += 32) {
        uint32_t ra[32], rb[32];
        TCGEN05_LD_32X32B_X32(ra, tmem + c0 + cb);
        TCGEN05_LD_32X32B_X32(rb, tmem + 256 + c0 + cb);
        TCGEN05_WAIT_LD();
        if (act) {
#pragma unroll
            for (int q = 0; q < 32; q += 4) {
                float o[4];
#pragma unroll
                for (int u = 0; u < 4; u++) {
                    float a = __uint_as_float(ra[q + u]);
                    float b = __uint_as_float(rb[q + u]);
                    o[u] = (a / (1.0f + expf(-a))) * b;
                }
                *(uint2*)(hrow + c0 + cb + q) =
                    make_uint2(h2u(__floats2half2_rn(o[0], o[1])),
                               h2u(__floats2half2_rn(o[2], o[3])));
            }
        }
    }
    __syncthreads();
    if (tid == 0)
#pragma unroll
        for (int b = 0; b < NSTG; b++) MBARRIER_INVAL(sb + S_MB + 8 * b);
    __syncthreads();
    if (wid == 0) TCGEN05_DEALLOC(tmem, 512);
#else
    // ---------- FFMA fallback (plain sm_103 pass) ----------
    int e = blockIdx.z, nt = blockIdx.y, m = blockIdx.x;
    int cnt = g_count[e];
    if (m * 128 >= cnt) return;
    extern __shared__ char smem[];
    float* As  = (float*)smem;
    float* B1s = As + 2048;
    float* B3s = B1s + 16 * 132;
    int tid = threadIdx.x;
    int tx = tid & 15, ty = tid >> 4;
    int n0 = nt * 256;
    const unsigned short* Ab = g_xa + ((size_t)e * T_TOK + (size_t)m * 128) * H_DIM;
    for (int nh = 0; nh < 2; nh++) {
        float a1[4][8], a3[4][8];
#pragma unroll
        for (int i = 0; i < 4; i++)
#pragma unroll
            for (int j = 0; j < 8; j++) { a1[i][j] = 0.f; a3[i][j] = 0.f; }
        for (int kc = 0; kc < H_DIM / 16; kc++) {
            __syncthreads();
#pragma unroll
            for (int L = 0; L < 4; L++) {
                int f = tid + NT * L;
                int row = f >> 4, k = f & 15;
                As[f] = __half2float(__ushort_as_half(Ab[(size_t)row * H_DIM + kc * 16 + k]));
            }
#pragma unroll
            for (int L = 0; L < 4; L++) {
                int f = tid + NT * L;
                int k = f >> 7, c = f & 127;
                B1s[k * 132 + c] = __half2float(__ushort_as_half(
                    g_w1t[((size_t)e * I_DIM + n0 + nh * 128 + c) * H_DIM + kc * 16 + k]));
                B3s[k * 132 + c] = __half2float(__ushort_as_half(
                    g_w3t[((size_t)e * I_DIM + n0 + nh * 128 + c) * H_DIM + kc * 16 + k]));
            }
            __syncthreads();
#pragma unroll
            for (int k = 0; k < 16; k++) {
                float av[4], b1[8], b3[8];
#pragma unroll
                for (int i = 0; i < 4; i++) av[i] = As[(ty * 4 + i) * 16 + k];
#pragma unroll
                for (int j = 0; j < 8; j++) {
                    b1[j] = B1s[k * 132 + tx * 8 + j];
                    b3[j] = B3s[k * 132 + tx * 8 + j];
                }
#pragma unroll
                for (int i = 0; i < 4; i++)
#pragma unroll
                    for (int j = 0; j < 8; j++) {
                        a1[i][j] += av[i] * b1[j];
                        a3[i][j] += av[i] * b3[j];
                    }
            }
        }
#pragma unroll
        for (int i = 0; i < 4; i++) {
            int row = ty * 4 + i, grow = m * 128 + row;
            if (grow < cnt) {
                unsigned short* hrow = g_h + ((size_t)e * T_TOK + grow) * I_DIM + n0 + nh * 128 + tx * 8;
#pragma unroll
                for (int j = 0; j < 8; j++) {
                    float a = a1[i][j];
                    hrow[j] = __half_as_ushort(__float2half_rn((a / (1.f + expf(-a))) * a3[i][j]));
                }
            }
        }
    }
#endif
}

// ---------------- grouped GEMM2 (g_h @ w2t, weighted scatter) ----------------
// M=128, N=512 (two N=256 accumulators = 512 TMEM cols)
__global__ void __launch_bounds__(NT, 1)
k_gemm2(float* __restrict__ out) {
#if HAS_TC
    int e = blockIdx.z, nt = blockIdx.y, m = blockIdx.x;
    int cnt = g_count[e];
    if (m * 128 >= cnt) return;

    extern __shared__ char smem[];
    uint32_t sb = smem_u32(smem);
    int tid = threadIdx.x, wid = tid >> 5, lid = tid & 31;

    if (tid < 128) {
        int r = m * 128 + tid;
        bool a = r < cnt;
        ((int*)(smem + S2_TOKS))[tid]  = a ? g_tok[e * T_TOK + r] : 0;
        ((float*)(smem + S2_WTS))[tid] = a ? g_wt[e * T_TOK + r] : 0.f;
    }
    if (wid == 0) { TCGEN05_ALLOC(sb, 512); TCGEN05_RELINQUISH(); }
    if (tid == 0)
#pragma unroll
        for (int b = 0; b < NSTG; b++) MBARRIER_INIT(sb + S_MB + 8 * b, 1);
    __syncthreads();
    uint32_t tmem;
    asm volatile("ld.shared.b32 %0, [%1];" : "=r"(tmem) : "r"(sb));

    int n0 = nt * 512;
    const unsigned short* Ab = g_h   + ((size_t)e * T_TOK + (size_t)m * 128) * I_DIM;
    const unsigned short* Bb = g_w2t + ((size_t)e * H_DIM + n0) * I_DIM;

    auto issue = [&](int buf, int kc) {
        uint32_t sA = sb + S2_BUF + buf * STG;
        uint32_t sB = sA + 8192;
        int ko = kc * 32;
        {                                                   // A: 512 chunks
            int row = tid >> 2, c4 = tid & 3;
            cpa16(sA + SW64(row * 64 + c4 * 16), Ab + (size_t)row * I_DIM + ko + c4 * 8);
        }
#pragma unroll
        for (int j = 0; j < 4; j++) {                       // B: 512 rows = 2048 chunks
            int idx = tid + NT * j;
            int n = idx >> 2, c4 = idx & 3;
            cpa16(sB + SW64(n * 64 + c4 * 16), Bb + (size_t)n * I_DIM + ko + c4 * 8);
        }
        CP_COMMIT();
    };

    issue(0, 0); issue(1, 1); issue(2, 2);

    const int NK = I_DIM / 32;  // 128
    for (int kc = 0; kc < NK; kc++) {
        int buf = kc & 3;
        int rem = NK - 1 - kc;
        if (rem >= 2) CP_WAIT2(); else if (rem == 1) CP_WAIT1(); else CP_WAIT0();
        if (tid == 0 && kc >= 1 && kc + 3 < NK) {
            int b = (kc + 3) & 3;
            int n = (kc - 1 - b) >> 2;
            MBARRIER_WAIT_PARITY(sb + S_MB + 8 * b, n & 1);
        }
        __syncthreads();
        if (wid == 0 && elect1()) {
            FENCE_ASYNC();
            uint32_t base = sb + S2_BUF + buf * STG;
            uint64_t ad    = mkdesc(base);
            uint64_t bd_lo = mkdesc(base + 8192);
            uint64_t bd_hi = mkdesc(base + 8192 + 16384);
#pragma unroll
            for (int s = 0; s < 2; s++) {
                uint32_t en = (kc > 0 || s > 0) ? 1u : 0u;
                mma_f16(tmem,       ad + s * 2, bd_lo + s * 2, en);
                mma_f16(tmem + 256, ad + s * 2, bd_hi + s * 2, en);
            }
            TCGEN05_COMMIT(sb + S_MB + 8 * buf);
        }
        if (kc + 3 < NK) issue((kc + 3) & 3, kc + 3);
    }
    {
        int bf = (NK - 1) & 3;
        int nf = (NK - 1 - bf) >> 2;
        MBARRIER_WAIT_PARITY(sb + S_MB + 8 * bf, nf & 1);
    }
    TCGEN05_FENCE_AFTER();

    // epilogue: weighted atomic scatter; 512 cols via 4 warpgroups x 128 cols
    int row = (wid & 3) * 32 + lid;
    int grow = m * 128 + row;
    bool act = grow < cnt;
    int tok = ((const int*)(smem + S2_TOKS))[row];
    float wt = ((const float*)(smem + S2_WTS))[row];
    int c0 = (wid >> 2) * 128;
    float* orow = out + (size_t)tok * H_DIM + n0;
#pragma unroll 1
    for (int cb = 0; cb < 128; cb += 32) {
        uint32_t r[32];
        uint32_t taddr = (c0 + cb < 256) ? (tmem + c0 + cb) : (tmem + 256 + (c0 + cb - 256));
        TCGEN05_LD_32X32B_X32(r, taddr);
        TCGEN05_WAIT_LD();
        if (act) {
#pragma unroll
            for (int q = 0; q < 32; q++)
                atomicAdd(&orow[c0 + cb + q], wt * __uint_as_float(r[q]));
        }
    }
    __syncthreads();
    if (tid == 0)
#pragma unroll
        for (int b = 0; b < NSTG; b++) MBARRIER_INVAL(sb + S_MB + 8 * b);
    __syncthreads();
    if (wid == 0) TCGEN05_DEALLOC(tmem, 512);
#else
    // ---------- FFMA fallback ----------
    int e = blockIdx.z, nt = blockIdx.y, m = blockIdx.x;
    int cnt = g_count[e];
    if (m * 128 >= cnt) return;
    extern __shared__ char smem[];
    float* As = (float*)smem;
    float* Bs = As + 2048;
    int tid = threadIdx.x;
    int tx = tid & 15, ty = tid >> 4;
    int n0 = nt * 512;
    const unsigned short* Ab = g_h + ((size_t)e * T_TOK + (size_t)m * 128) * I_DIM;
    for (int nh = 0; nh < 4; nh++) {
        float acc[4][8];
#pragma unroll
        for (int i = 0; i < 4; i++)
#pragma unroll
            for (int j = 0; j < 8; j++) acc[i][j] = 0.f;
        for (int kc = 0; kc < I_DIM / 16; kc++) {
            __syncthreads();
#pragma unroll
            for (int L = 0; L < 4; L++) {
                int f = tid + NT * L;
                int row = f >> 4, k = f & 15;
                As[f] = __half2float(__ushort_as_half(Ab[(size_t)row * I_DIM + kc * 16 + k]));
            }
#pragma unroll
            for (int L = 0; L < 4; L++) {
                int f = tid + NT * L;
                int k = f >> 7, c = f & 127;
                Bs[k * 132 + c] = __half2float(__ushort_as_half(
                    g_w2t[((size_t)e * H_DIM + n0 + nh * 128 + c) * I_DIM + kc * 16 + k]));
            }
            __syncthreads();
#pragma unroll
            for (int k = 0; k < 16; k++) {
                float av[4], b[8];
#pragma unroll
                for (int i = 0; i < 4; i++) av[i] = As[(ty * 4 + i) * 16 + k];
#pragma unroll
                for (int j = 0; j < 8; j++) b[j] = Bs[k * 132 + tx * 8 + j];
#pragma unroll
                for (int i = 0; i < 4; i++)
#pragma unroll
                    for (int j = 0; j < 8; j++) acc[i][j] += av[i] * b[j];
            }
        }
#pragma unroll
        for (int i = 0; i < 4; i++) {
            int row = ty * 4 + i, grow = m * 128 + row;
            if (grow < cnt) {
                int tok = g_tok[e * T_TOK + grow];
                float wt = g_wt[e * T_TOK + grow];
                float* orow = out + (size_t)tok * H_DIM + n0 + nh * 128 + tx * 8;
#pragma unroll
                for (int j = 0; j < 8; j++)
                    atomicAdd(&orow[j], wt * acc[i][j]);
            }
        }
    }
#endif
}

// ---------------- launch ----------------
extern "C" void kernel_launch(void* const* d_in, const int* in_sizes, int n_in,
                              void* d_out, int out_size) {
    const float* x  = (const float*)d_in[0];   // hidden_states [T,H]
    const float* gw = (const float*)d_in[1];   // gate_w [H,E]
    const float* w1 = (const float*)d_in[2];   // [E,H,I]
    const float* w3 = (const float*)d_in[3];   // [E,H,I]
    const float* w2 = (const float*)d_in[4];   // [E,I,H]
    float* out = (float*)d_out;

    cudaFuncSetAttribute(k_gemm1, cudaFuncAttributeMaxDynamicSharedMemorySize, S_SMEM);
    cudaFuncSetAttribute(k_gemm2, cudaFuncAttributeMaxDynamicSharedMemorySize, S2_SMEM);

    k_zero<<<T_TOK * H_DIM / 4 / 256, 256>>>(out);
    k_gate<<<T_TOK, 256>>>(x, gw);
    k_tr13<<<dim3(I_DIM / 32, H_DIM / 32, 2 * E_NUM), 256>>>(w1, w3);
    k_tr2 <<<dim3(H_DIM / 32, I_DIM / 32, E_NUM), 256>>>(w2);
    k_pack<<<dim3(T_TOK / 8, E_NUM), 256>>>(x);
    // grid.x = m-slot (fastest -> co-resident CTAs share (e,n) B stream in L2)
    k_gemm1<<<dim3(T_TOK / 128, I_DIM / 256, E_NUM), NT, S_SMEM>>>();
    k_gemm2<<<dim3(T_TOK / 128, H_DIM / 512, E_NUM), NT, S2_SMEM>>>(out);
}

// round 9
// speedup vs baseline: 2.4902x; 1.0619x over previous
#include <cuda_runtime.h>
#include <cuda_fp16.h>
#include <cstdint>

// ---------------- problem constants ----------------
#define T_TOK 8192          // B*S
#define H_DIM 1024
#define E_NUM 8
#define I_DIM 4096
#define NT 512              // threads per GEMM CTA

// tcgen05 only legal in the sm_103a arch-accelerated pass
#if !defined(__CUDA_ARCH__) || defined(__CUDA_ARCH_FEAT_SM103_ALL)
#define HAS_TC 1
#else
#define HAS_TC 0
#endif

// ---------------- device scratch (static, allocation-free; halves as u16) ----
__device__ int            g_count[E_NUM];
__device__ int            g_tok[E_NUM * T_TOK];
__device__ float          g_wt [E_NUM * T_TOK];
__device__ unsigned short g_h  [268435456];                       // [E*T, I] half
__device__ unsigned short g_xa [(size_t)E_NUM * T_TOK * H_DIM];   // gathered x half
__device__ unsigned short g_w1t[(size_t)E_NUM * I_DIM * H_DIM];   // [E][I][H] half
__device__ unsigned short g_w3t[(size_t)E_NUM * I_DIM * H_DIM];
__device__ unsigned short g_w2t[(size_t)E_NUM * H_DIM * I_DIM];   // [E][H][I] half

#define SW64(x) ((x) ^ (((x) >> 3) & 0x30))

// bit-cast __half2 -> u32
__device__ __forceinline__ uint32_t h2u(__half2 h) {
    __half2_raw r = *reinterpret_cast<__half2_raw*>(&h);
    return (uint32_t)r.x | ((uint32_t)r.y << 16);
}

#if HAS_TC
__device__ __forceinline__ uint32_t smem_u32(const void* p) {
    uint32_t a;
    asm("{ .reg .u64 t; cvta.to.shared.u64 t, %1; cvt.u32.u64 %0, t; }"
        : "=r"(a) : "l"(p));
    return a;
}
__device__ __forceinline__ uint32_t elect1() {
    uint32_t p;
    asm volatile("{ .reg .pred p; elect.sync _|p, 0xFFFFFFFF; selp.b32 %0,1,0,p; }" : "=r"(p));
    return p;
}
__device__ __forceinline__ void cpa16(uint32_t dst, const void* src) {
    asm volatile("cp.async.cg.shared.global [%0], [%1], 16;" :: "r"(dst), "l"(src));
}
#define CP_COMMIT() asm volatile("cp.async.commit_group;" ::: "memory")
#define CP_WAIT2()  asm volatile("cp.async.wait_group 2;" ::: "memory")
#define CP_WAIT1()  asm volatile("cp.async.wait_group 1;" ::: "memory")
#define CP_WAIT0()  asm volatile("cp.async.wait_group 0;" ::: "memory")

// SW64 K-major smem descriptor (Blackwell): layout=4, version=1, SBO=32, LBO=1
static constexpr uint64_t DESC_BASE64 =
    (4ull << 61) | (1ull << 46) | (32ull << 32) | (1ull << 16);
__device__ __forceinline__ uint64_t mkdesc(uint32_t smem_addr) {
    return DESC_BASE64 | ((uint64_t)(smem_addr >> 4) & 0x3FFF);
}
// f16 idesc (cg1): D=F32(1<<4), A=FP16, B=FP16, M=128 (8<<24)
static constexpr uint32_t IDESC_F16_N128 = (1u << 4) | (16u << 17) | (8u << 24);
static constexpr uint32_t IDESC_F16_N256 = (1u << 4) | (32u << 17) | (8u << 24);

__device__ __forceinline__ void mma_f16(uint32_t d_tmem, uint64_t a_desc,
                                        uint64_t b_desc, uint32_t idesc,
                                        uint32_t en) {
    asm volatile(
        "{\n\t"
        ".reg .pred p;\n\t"
        "setp.ne.u32 p, %4, 0;\n\t"
        "tcgen05.mma.cta_group::1.kind::f16 [%0], %1, %2, %3, {%5,%5,%5,%5}, p;\n\t"
        "}"
        :: "r"(d_tmem), "l"(a_desc), "l"(b_desc), "r"(idesc),
           "r"(en), "r"(0u)
        : "memory");
}

#define TCGEN05_ALLOC(a, n) \
    asm volatile("tcgen05.alloc.cta_group::1.sync.aligned.shared::cta.b32 [%0], %1;" \
        :: "r"((uint32_t)(a)), "r"((uint32_t)(n)) : "memory")
#define TCGEN05_RELINQUISH() \
    asm volatile("tcgen05.relinquish_alloc_permit.cta_group::1.sync.aligned;")
#define TCGEN05_DEALLOC(t, n) \
    asm volatile("tcgen05.dealloc.cta_group::1.sync.aligned.b32 %0, %1;" \
        :: "r"(t), "r"((uint32_t)(n)))
#define TCGEN05_COMMIT(mbar) \
    asm volatile("tcgen05.commit.cta_group::1.mbarrier::arrive::one.shared::cluster.b64 [%0];" \
        :: "r"((uint32_t)(mbar)) : "memory")
#define TCGEN05_FENCE_AFTER() \
    asm volatile("tcgen05.fence::after_thread_sync;" ::: "memory")
#define TCGEN05_WAIT_LD() \
    asm volatile("tcgen05.wait::ld.sync.aligned;" ::: "memory")
#define FENCE_ASYNC() \
    asm volatile("fence.proxy.async.shared::cta;" ::: "memory")

#define MBARRIER_INIT(a, c) \
    asm volatile("mbarrier.init.shared.b64 [%0], %1;" \
        :: "r"((uint32_t)(a)), "r"((uint32_t)(c)) : "memory")
#define MBARRIER_INVAL(a) \
    asm volatile("mbarrier.inval.shared.b64 [%0];" \
        :: "r"((uint32_t)(a)) : "memory")

#define MBARRIER_WAIT_PARITY(mbar_smem_addr, phase_parity) do { \
    uint32_t _mbar = (uint32_t)(mbar_smem_addr); \
    uint32_t _parity = (uint32_t)(phase_parity); \
    uint32_t _done; \
    asm volatile( \
        "{\n\t" \
        ".reg .pred p;\n\t" \
        "mbarrier.try_wait.parity.acquire.cta.shared::cta.b64 p, [%1], %2;\n\t" \
        "selp.b32 %0, 1, 0, p;\n\t" \
        "}" \
        : "=r"(_done) : "r"(_mbar), "r"(_parity) : "memory"); \
    if (!_done) { \
        asm volatile( \
            "{\n\t" \
            ".reg .pred P1;\n\t" \
            "WAIT_LOOP_%=:\n\t" \
            "mbarrier.try_wait.parity.acquire.cta.shared::cta.b64 P1, [%0], %1, 0x989680;\n\t" \
            "@P1 bra.uni WAIT_DONE_%=;\n\t" \
            "bra.uni WAIT_LOOP_%=;\n\t" \
            "WAIT_DONE_%=:\n\t" \
            "}" \
            :: "r"(_mbar), "r"(_parity) : "memory"); \
    } \
} while (0)

#define TCGEN05_LD_32X32B_X16(r, tmem_addr) \
    asm volatile( \
        "tcgen05.ld.sync.aligned.32x32b.x16.b32 " \
        "{%0, %1, %2, %3, %4, %5, %6, %7, " \
        " %8, %9, %10, %11, %12, %13, %14, %15}, [%16];" \
        : "=r"((r)[0]),  "=r"((r)[1]),  "=r"((r)[2]),  "=r"((r)[3]), \
          "=r"((r)[4]),  "=r"((r)[5]),  "=r"((r)[6]),  "=r"((r)[7]), \
          "=r"((r)[8]),  "=r"((r)[9]),  "=r"((r)[10]), "=r"((r)[11]), \
          "=r"((r)[12]), "=r"((r)[13]), "=r"((r)[14]), "=r"((r)[15]) \
        : "r"(tmem_addr))
#endif  // HAS_TC

// ---------------- kernel 0: zero out + counters ----------------
__global__ void k_zero(float* __restrict__ out) {
    size_t i = (size_t)blockIdx.x * blockDim.x + threadIdx.x;
    float4* o4 = (float4*)out;
    if (i < (size_t)T_TOK * H_DIM / 4) o4[i] = make_float4(0.f, 0.f, 0.f, 0.f);
    if (blockIdx.x == 0 && threadIdx.x < E_NUM) g_count[threadIdx.x] = 0;
}

// ---------------- kernel 1: gating (softmax top-2, routing lists) ----------------
__global__ void k_gate(const float* __restrict__ x, const float* __restrict__ gw) {
    int t = blockIdx.x;
    const float* xr = x + (size_t)t * H_DIM;
    float acc[E_NUM];
#pragma unroll
    for (int e = 0; e < E_NUM; e++) acc[e] = 0.f;
    for (int h = threadIdx.x; h < H_DIM; h += 256) {
        float xv = xr[h];
        const float* g = gw + h * E_NUM;
#pragma unroll
        for (int e = 0; e < E_NUM; e++) acc[e] += xv * g[e];
    }
#pragma unroll
    for (int e = 0; e < E_NUM; e++)
#pragma unroll
        for (int off = 16; off > 0; off >>= 1)
            acc[e] += __shfl_xor_sync(0xFFFFFFFF, acc[e], off);
    __shared__ float red[8][E_NUM];
    int wid = threadIdx.x >> 5, lid = threadIdx.x & 31;
    if (lid == 0)
#pragma unroll
        for (int e = 0; e < E_NUM; e++) red[wid][e] = acc[e];
    __syncthreads();
    if (threadIdx.x == 0) {
        float l[E_NUM];
#pragma unroll
        for (int e = 0; e < E_NUM; e++) {
            float s = 0.f;
#pragma unroll
            for (int w = 0; w < 8; w++) s += red[w][e];
            l[e] = s;
        }
        int i1 = 0;
#pragma unroll
        for (int e = 1; e < E_NUM; e++) if (l[e] > l[i1]) i1 = e;
        int i2 = (i1 == 0) ? 1 : 0;
#pragma unroll
        for (int e = 0; e < E_NUM; e++) if (e != i1 && l[e] > l[i2]) i2 = e;
        float e2 = expf(l[i2] - l[i1]);
        float wa = 1.f / (1.f + e2);
        float wb = 1.f - wa;
        int p1 = atomicAdd(&g_count[i1], 1);
        g_tok[i1 * T_TOK + p1] = t;  g_wt[i1 * T_TOK + p1] = wa;
        int p2 = atomicAdd(&g_count[i2], 1);
        g_tok[i2 * T_TOK + p2] = t;  g_wt[i2 * T_TOK + p2] = wb;
    }
}

// ---------------- prep: transpose + fp16-convert weights ----------------
__global__ void k_tr13(const float* __restrict__ w1, const float* __restrict__ w3) {
    __shared__ float tile[32][33];
    int e = blockIdx.z & 7;
    const float* src = (blockIdx.z < E_NUM ? w1 : w3) + (size_t)e * H_DIM * I_DIM;
    unsigned short* dst = (blockIdx.z < E_NUM ? g_w1t : g_w3t) + (size_t)e * I_DIM * H_DIM;
    int i0 = blockIdx.x * 32, h0 = blockIdx.y * 32;
    int tx = threadIdx.x & 31, ty = threadIdx.x >> 5;
#pragma unroll
    for (int r = 0; r < 32; r += 8)
        tile[ty + r][tx] = src[(size_t)(h0 + ty + r) * I_DIM + i0 + tx];
    __syncthreads();
#pragma unroll
    for (int r = 0; r < 32; r += 8)
        dst[(size_t)(i0 + ty + r) * H_DIM + h0 + tx] =
            __half_as_ushort(__float2half_rn(tile[tx][ty + r]));
}
__global__ void k_tr2(const float* __restrict__ w2) {
    __shared__ float tile[32][33];
    int e = blockIdx.z;
    const float* src = w2 + (size_t)e * I_DIM * H_DIM;
    unsigned short* dst = g_w2t + (size_t)e * H_DIM * I_DIM;
    int h0 = blockIdx.x * 32, i0 = blockIdx.y * 32;
    int tx = threadIdx.x & 31, ty = threadIdx.x >> 5;
#pragma unroll
    for (int r = 0; r < 32; r += 8)
        tile[ty + r][tx] = src[(size_t)(i0 + ty + r) * H_DIM + h0 + tx];
    __syncthreads();
#pragma unroll
    for (int r = 0; r < 32; r += 8)
        dst[(size_t)(h0 + ty + r) * I_DIM + i0 + tx] =
            __half_as_ushort(__float2half_rn(tile[tx][ty + r]));
}

// ---------------- pack: gather + fp16-round x rows per expert slot ----------------
__global__ void k_pack(const float* __restrict__ x) {
    int e = blockIdx.y;
    int cnt = g_count[e];
    int slot = blockIdx.x * 8 + (threadIdx.x >> 5);
    int c = threadIdx.x & 31;
    if (slot >= cnt) return;
    int tok = g_tok[e * T_TOK + slot];
    const float4* src = (const float4*)(x + (size_t)tok * H_DIM);
    uint2* dst = (uint2*)(g_xa + ((size_t)e * T_TOK + slot) * H_DIM);
#pragma unroll
    for (int j = 0; j < 8; j++) {
        float4 v = src[c + 32 * j];
        dst[c + 32 * j] = make_uint2(h2u(__floats2half2_rn(v.x, v.y)),
                                     h2u(__floats2half2_rn(v.z, v.w)));
    }
}

// ---------------- GEMM geometry (f16, SW64, 4-stage, 2 CTAs/SM) ----------------
// K-chunk = 32 halves; stage 24KB; 4-stage ring, lookahead 3.
// TMEM 256 cols/CTA -> two CTAs share an SM (512-col budget).
#define NSTG    4
#define S_MB    16
#define S1_BUF  1024
#define STG1    24576                    // GEMM1: A 8K + B1 8K + B3 8K
#define S_SMEM  (S1_BUF + NSTG * STG1)   // 99328
#define S2_TOKS 64
#define S2_WTS  576
#define S2_BUF  2048
#define STG2    24576                    // GEMM2: A 8K + B 16K
#define S2_SMEM (S2_BUF + NSTG * STG2)   // 100352

// ---------------- grouped GEMM1 (xa@w1t, xa@w3t, SwiGLU -> g_h half) ---------
// M=128, N=128 I-cols; d1 @ tmem+0, d3 @ tmem+128 (256 TMEM cols)
__global__ void __launch_bounds__(NT, 2)
k_gemm1() {
#if HAS_TC
    int e = blockIdx.z, nt = blockIdx.y, m = blockIdx.x;
    int cnt = g_count[e];
    if (m * 128 >= cnt) return;

    extern __shared__ char smem[];
    uint32_t sb = smem_u32(smem);
    int tid = threadIdx.x, wid = tid >> 5, lid = tid & 31;

    if (wid == 0) { TCGEN05_ALLOC(sb, 256); TCGEN05_RELINQUISH(); }
    if (tid == 0)
#pragma unroll
        for (int b = 0; b < NSTG; b++) MBARRIER_INIT(sb + S_MB + 8 * b, 1);
    __syncthreads();
    uint32_t tmem;
    asm volatile("ld.shared.b32 %0, [%1];" : "=r"(tmem) : "r"(sb));

    int n0 = nt * 128;
    const unsigned short* Ab  = g_xa  + ((size_t)e * T_TOK + (size_t)m * 128) * H_DIM;
    const unsigned short* B1b = g_w1t + ((size_t)e * I_DIM + n0) * H_DIM;
    const unsigned short* B3b = g_w3t + ((size_t)e * I_DIM + n0) * H_DIM;

    auto issue = [&](int buf, int kc) {
        uint32_t sA  = sb + S1_BUF + buf * STG1;
        uint32_t sB1 = sA + 8192;
        uint32_t sB3 = sB1 + 8192;
        int ko = kc * 32;                                   // halves
        int row = tid >> 2, c4 = tid & 3;
        cpa16(sA  + SW64(row * 64 + c4 * 16), Ab  + (size_t)row * H_DIM + ko + c4 * 8);
        cpa16(sB1 + SW64(row * 64 + c4 * 16), B1b + (size_t)row * H_DIM + ko + c4 * 8);
        cpa16(sB3 + SW64(row * 64 + c4 * 16), B3b + (size_t)row * H_DIM + ko + c4 * 8);
        CP_COMMIT();
    };

    issue(0, 0); issue(1, 1); issue(2, 2);

    const int NK = H_DIM / 32;  // 32
    for (int kc = 0; kc < NK; kc++) {
        int buf = kc & 3;
        int rem = NK - 1 - kc;
        if (rem >= 2) CP_WAIT2(); else if (rem == 1) CP_WAIT1(); else CP_WAIT0();
        if (tid == 0 && kc >= 1 && kc + 3 < NK) {
            int b = (kc + 3) & 3;
            int n = (kc - 1 - b) >> 2;
            MBARRIER_WAIT_PARITY(sb + S_MB + 8 * b, n & 1);
        }
        __syncthreads();
        if (wid == 0 && elect1()) {
            FENCE_ASYNC();
            uint32_t base = sb + S1_BUF + buf * STG1;
            uint64_t ad  = mkdesc(base);
            uint64_t bd1 = mkdesc(base + 8192);
            uint64_t bd3 = mkdesc(base + 16384);
#pragma unroll
            for (int s = 0; s < 2; s++) {                   // 2 x K=16
                uint32_t en = (kc > 0 || s > 0) ? 1u : 0u;
                mma_f16(tmem,       ad + s * 2, bd1 + s * 2, IDESC_F16_N128, en);
                mma_f16(tmem + 128, ad + s * 2, bd3 + s * 2, IDESC_F16_N128, en);
            }
            TCGEN05_COMMIT(sb + S_MB + 8 * buf);
        }
        if (kc + 3 < NK) issue((kc + 3) & 3, kc + 3);
    }
    {
        int bf = (NK - 1) & 3;
        int nf = (NK - 1 - bf) >> 2;
        MBARRIER_WAIT_PARITY(sb + S_MB + 8 * bf, nf & 1);
    }
    TCGEN05_FENCE_AFTER();

    // epilogue: silu(d1)*d3 -> half -> g_h. 4 warpgroups x 32 cols, x16 loads.
    int row = (wid & 3) * 32 + lid;
    int grow = m * 128 + row;
    bool act = grow < cnt;
    int c0 = (wid >> 2) * 32;
    unsigned short* hrow = g_h + ((size_t)e * T_TOK + grow) * I_DIM + n0;
#pragma unroll 1
    for (int cb = 0; cb < 32; cb += 16) {
        uint32_t ra[16], rb[16];
        TCGEN05_LD_32X32B_X16(ra, tmem + c0 + cb);
        TCGEN05_LD_32X32B_X16(rb, tmem + 128 + c0 + cb);
        TCGEN05_WAIT_LD();
        if (act) {
#pragma unroll
            for (int q = 0; q < 16; q += 4) {
                float o[4];
#pragma unroll
                for (int u = 0; u < 4; u++) {
                    float a = __uint_as_float(ra[q + u]);
                    float b = __uint_as_float(rb[q + u]);
                    o[u] = (a / (1.0f + expf(-a))) * b;
                }
                *(uint2*)(hrow + c0 + cb + q) =
                    make_uint2(h2u(__floats2half2_rn(o[0], o[1])),
                               h2u(__floats2half2_rn(o[2], o[3])));
            }
        }
    }
    __syncthreads();
    if (tid == 0)
#pragma unroll
        for (int b = 0; b < NSTG; b++) MBARRIER_INVAL(sb + S_MB + 8 * b);
    __syncthreads();
    if (wid == 0) TCGEN05_DEALLOC(tmem, 256);
#else
    // ---------- FFMA fallback (plain sm_103 pass) ----------
    int e = blockIdx.z, nt = blockIdx.y, m = blockIdx.x;
    int cnt = g_count[e];
    if (m * 128 >= cnt) return;
    extern __shared__ char smem[];
    float* As  = (float*)smem;
    float* B1s = As + 2048;
    float* B3s = B1s + 16 * 132;
    int tid = threadIdx.x;
    int tx = tid & 15, ty = tid >> 4;
    int n0 = nt * 128;
    const unsigned short* Ab = g_xa + ((size_t)e * T_TOK + (size_t)m * 128) * H_DIM;
    {
        float a1[4][8], a3[4][8];
#pragma unroll
        for (int i = 0; i < 4; i++)
#pragma unroll
            for (int j = 0; j < 8; j++) { a1[i][j] = 0.f; a3[i][j] = 0.f; }
        for (int kc = 0; kc < H_DIM / 16; kc++) {
            __syncthreads();
#pragma unroll
            for (int L = 0; L < 4; L++) {
                int f = tid + NT * L;
                int row = f >> 4, k = f & 15;
                As[f] = __half2float(__ushort_as_half(Ab[(size_t)row * H_DIM + kc * 16 + k]));
            }
#pragma unroll
            for (int L = 0; L < 4; L++) {
                int f = tid + NT * L;
                int k = f >> 7, c = f & 127;
                B1s[k * 132 + c] = __half2float(__ushort_as_half(
                    g_w1t[((size_t)e * I_DIM + n0 + c) * H_DIM + kc * 16 + k]));
                B3s[k * 132 + c] = __half2float(__ushort_as_half(
                    g_w3t[((size_t)e * I_DIM + n0 + c) * H_DIM + kc * 16 + k]));
            }
            __syncthreads();
#pragma unroll
            for (int k = 0; k < 16; k++) {
                float av[4], b1[8], b3[8];
#pragma unroll
                for (int i = 0; i < 4; i++) av[i] = As[(ty * 4 + i) * 16 + k];
#pragma unroll
                for (int j = 0; j < 8; j++) {
                    b1[j] = B1s[k * 132 + tx * 8 + j];
                    b3[j] = B3s[k * 132 + tx * 8 + j];
                }
#pragma unroll
                for (int i = 0; i < 4; i++)
#pragma unroll
                    for (int j = 0; j < 8; j++) {
                        a1[i][j] += av[i] * b1[j];
                        a3[i][j] += av[i] * b3[j];
                    }
            }
        }
#pragma unroll
        for (int i = 0; i < 4; i++) {
            int row = ty * 4 + i, grow = m * 128 + row;
            if (grow < cnt) {
                unsigned short* hrow = g_h + ((size_t)e * T_TOK + grow) * I_DIM + n0 + tx * 8;
#pragma unroll
                for (int j = 0; j < 8; j++) {
                    float a = a1[i][j];
                    hrow[j] = __half_as_ushort(__float2half_rn((a / (1.f + expf(-a))) * a3[i][j]));
                }
            }
        }
    }
#endif
}

// ---------------- grouped GEMM2 (g_h @ w2t, weighted scatter) ----------------
// M=128, N=256 (single accumulator = 256 TMEM cols)
__global__ void __launch_bounds__(NT, 2)
k_gemm2(float* __restrict__ out) {
#if HAS_TC
    int e = blockIdx.z, nt = blockIdx.y, m = blockIdx.x;
    int cnt = g_count[e];
    if (m * 128 >= cnt) return;

    extern __shared__ char smem[];
    uint32_t sb = smem_u32(smem);
    int tid = threadIdx.x, wid = tid >> 5, lid = tid & 31;

    if (tid < 128) {
        int r = m * 128 + tid;
        bool a = r < cnt;
        ((int*)(smem + S2_TOKS))[tid]  = a ? g_tok[e * T_TOK + r] : 0;
        ((float*)(smem + S2_WTS))[tid] = a ? g_wt[e * T_TOK + r] : 0.f;
    }
    if (wid == 0) { TCGEN05_ALLOC(sb, 256); TCGEN05_RELINQUISH(); }
    if (tid == 0)
#pragma unroll
        for (int b = 0; b < NSTG; b++) MBARRIER_INIT(sb + S_MB + 8 * b, 1);
    __syncthreads();
    uint32_t tmem;
    asm volatile("ld.shared.b32 %0, [%1];" : "=r"(tmem) : "r"(sb));

    int n0 = nt * 256;
    const unsigned short* Ab = g_h   + ((size_t)e * T_TOK + (size_t)m * 128) * I_DIM;
    const unsigned short* Bb = g_w2t + ((size_t)e * H_DIM + n0) * I_DIM;

    auto issue = [&](int buf, int kc) {
        uint32_t sA = sb + S2_BUF + buf * STG2;
        uint32_t sB = sA + 8192;
        int ko = kc * 32;
        {
            int row = tid >> 2, c4 = tid & 3;
            cpa16(sA + SW64(row * 64 + c4 * 16), Ab + (size_t)row * I_DIM + ko + c4 * 8);
        }
#pragma unroll
        for (int j = 0; j < 2; j++) {                       // B: 256 rows = 1024 chunks
            int idx = tid + NT * j;
            int n = idx >> 2, c4 = idx & 3;
            cpa16(sB + SW64(n * 64 + c4 * 16), Bb + (size_t)n * I_DIM + ko + c4 * 8);
        }
        CP_COMMIT();
    };

    issue(0, 0); issue(1, 1); issue(2, 2);

    const int NK = I_DIM / 32;  // 128
    for (int kc = 0; kc < NK; kc++) {
        int buf = kc & 3;
        int rem = NK - 1 - kc;
        if (rem >= 2) CP_WAIT2(); else if (rem == 1) CP_WAIT1(); else CP_WAIT0();
        if (tid == 0 && kc >= 1 && kc + 3 < NK) {
            int b = (kc + 3) & 3;
            int n = (kc - 1 - b) >> 2;
            MBARRIER_WAIT_PARITY(sb + S_MB + 8 * b, n & 1);
        }
        __syncthreads();
        if (wid == 0 && elect1()) {
            FENCE_ASYNC();
            uint32_t base = sb + S2_BUF + buf * STG2;
            uint64_t ad = mkdesc(base);
            uint64_t bd = mkdesc(base + 8192);
#pragma unroll
            for (int s = 0; s < 2; s++) {
                uint32_t en = (kc > 0 || s > 0) ? 1u : 0u;
                mma_f16(tmem, ad + s * 2, bd + s * 2, IDESC_F16_N256, en);
            }
            TCGEN05_COMMIT(sb + S_MB + 8 * buf);
        }
        if (kc + 3 < NK) issue((kc + 3) & 3, kc + 3);
    }
    {
        int bf = (NK - 1) & 3;
        int nf = (NK - 1 - bf) >> 2;
        MBARRIER_WAIT_PARITY(sb + S_MB + 8 * bf, nf & 1);
    }
    TCGEN05_FENCE_AFTER();

    // epilogue: weighted atomic scatter; 4 warpgroups x 64 cols, x16 loads
    int row = (wid & 3) * 32 + lid;
    int grow = m * 128 + row;
    bool act = grow < cnt;
    int tok = ((const int*)(smem + S2_TOKS))[row];
    float wt = ((const float*)(smem + S2_WTS))[row];
    int c0 = (wid >> 2) * 64;
    float* orow = out + (size_t)tok * H_DIM + n0;
#pragma unroll 1
    for (int cb = 0; cb < 64; cb += 16) {
        uint32_t r[16];
        TCGEN05_LD_32X32B_X16(r, tmem + c0 + cb);
        TCGEN05_WAIT_LD();
        if (act) {
#pragma unroll
            for (int q = 0; q < 16; q++)
                atomicAdd(&orow[c0 + cb + q], wt * __uint_as_float(r[q]));
        }
    }
    __syncthreads();
    if (tid == 0)
#pragma unroll
        for (int b = 0; b < NSTG; b++) MBARRIER_INVAL(sb + S_MB + 8 * b);
    __syncthreads();
    if (wid == 0) TCGEN05_DEALLOC(tmem, 256);
#else
    // ---------- FFMA fallback ----------
    int e = blockIdx.z, nt = blockIdx.y, m = blockIdx.x;
    int cnt = g_count[e];
    if (m * 128 >= cnt) return;
    extern __shared__ char smem[];
    float* As = (float*)smem;
    float* Bs = As + 2048;
    int tid = threadIdx.x;
    int tx = tid & 15, ty = tid >> 4;
    int n0 = nt * 256;
    const unsigned short* Ab = g_h + ((size_t)e * T_TOK + (size_t)m * 128) * I_DIM;
    for (int nh = 0; nh < 2; nh++) {
        float acc[4][8];
#pragma unroll
        for (int i = 0; i < 4; i++)
#pragma unroll
            for (int j = 0; j < 8; j++) acc[i][j] = 0.f;
        for (int kc = 0; kc < I_DIM / 16; kc++) {
            __syncthreads();
#pragma unroll
            for (int L = 0; L < 4; L++) {
                int f = tid + NT * L;
                int row = f >> 4, k = f & 15;
                As[f] = __half2float(__ushort_as_half(Ab[(size_t)row * I_DIM + kc * 16 + k]));
            }
#pragma unroll
            for (int L = 0; L < 4; L++) {
                int f = tid + NT * L;
                int k = f >> 7, c = f & 127;
                Bs[k * 132 + c] = __half2float(__ushort_as_half(
                    g_w2t[((size_t)e * H_DIM + n0 + nh * 128 + c) * I_DIM + kc * 16 + k]));
            }
            __syncthreads();
#pragma unroll
            for (int k = 0; k < 16; k++) {
                float av[4], b[8];
#pragma unroll
                for (int i = 0; i < 4; i++) av[i] = As[(ty * 4 + i) * 16 + k];
#pragma unroll
                for (int j = 0; j < 8; j++) b[j] = Bs[k * 132 + tx * 8 + j];
#pragma unroll
                for (int i = 0; i < 4; i++)
#pragma unroll
                    for (int j = 0; j < 8; j++) acc[i][j] += av[i] * b[j];
            }
        }
#pragma unroll
        for (int i = 0; i < 4; i++) {
            int row = ty * 4 + i, grow = m * 128 + row;
            if (grow < cnt) {
                int tok = g_tok[e * T_TOK + grow];
                float wt = g_wt[e * T_TOK + grow];
                float* orow = out + (size_t)tok * H_DIM + n0 + nh * 128 + tx * 8;
#pragma unroll
                for (int j = 0; j < 8; j++)
                    atomicAdd(&orow[j], wt * acc[i][j]);
            }
        }
    }
#endif
}

// ---------------- launch ----------------
extern "C" void kernel_launch(void* const* d_in, const int* in_sizes, int n_in,
                              void* d_out, int out_size) {
    const float* x  = (const float*)d_in[0];   // hidden_states [T,H]
    const float* gw = (const float*)d_in[1];   // gate_w [H,E]
    const float* w1 = (const float*)d_in[2];   // [E,H,I]
    const float* w3 = (const float*)d_in[3];   // [E,H,I]
    const float* w2 = (const float*)d_in[4];   // [E,I,H]
    float* out = (float*)d_out;

    cudaFuncSetAttribute(k_gemm1, cudaFuncAttributeMaxDynamicSharedMemorySize, S_SMEM);
    cudaFuncSetAttribute(k_gemm2, cudaFuncAttributeMaxDynamicSharedMemorySize, S2_SMEM);

    k_zero<<<T_TOK * H_DIM / 4 / 256, 256>>>(out);
    k_gate<<<T_TOK, 256>>>(x, gw);
    k_tr13<<<dim3(I_DIM / 32, H_DIM / 32, 2 * E_NUM), 256>>>(w1, w3);
    k_tr2 <<<dim3(H_DIM / 32, I_DIM / 32, E_NUM), 256>>>(w2);
    k_pack<<<dim3(T_TOK / 8, E_NUM), 256>>>(x);
    // grid.x = m-slot (fastest -> co-resident CTAs share (e,n) B stream in L2)
    k_gemm1<<<dim3(T_TOK / 128, I_DIM / 128, E_NUM), NT, S_SMEM>>>();
    k_gemm2<<<dim3(T_TOK / 128, H_DIM / 256, E_NUM), NT, S2_SMEM>>>(out);
}